// round 8
// baseline (speedup 1.0000x reference)
#include <cuda_runtime.h>
#include <cuda_bf16.h>

#define BSZ 8
#define LEN 4096
#define DM  128   // d_model (M)
#define DS  128   // d_state (N)

#define TO 1024   // output tile (time) per CTA
#define TU 128    // input tile (time)
#define NT 128    // threads per CTA (conv) -> 4 warps, all 4 SMSPs
#define RR 8      // output rows (l = t0 + tid + r*128) per thread

// -------- scratch (__device__ globals; no allocation allowed) --------
__device__ float g_xt[BSZ * DM * LEN];    // x transposed to (b, m, l)
__device__ float g_psum[DS * LEN];        // Psum[k, l]
__device__ float g_kern[DM * LEN];        // kernel[m, l]
__device__ float g_G[DM * DS];            // G = C @ B

using u64 = unsigned long long;
__device__ __forceinline__ void ffma2(u64 &d, u64 a, u64 b) {
    asm("fma.rn.f32x2 %0, %1, %2, %0;" : "+l"(d) : "l"(a), "l"(b));
}
__device__ __forceinline__ u64 pack2(float lo, float hi) {
    u64 r; asm("mov.b64 %0, {%1, %2};" : "=l"(r) : "f"(lo), "f"(hi)); return r;
}
__device__ __forceinline__ void unpack2(u64 v, float &lo, float &hi) {
    asm("mov.b64 {%0, %1}, %2;" : "=f"(lo), "=f"(hi) : "l"(v));
}

// -------- 1) transpose x (b,l,m) -> (b,m,l) --------
__global__ void transpose_kernel(const float* __restrict__ x) {
    __shared__ float tile[32][33];
    int b  = blockIdx.z;
    int l0 = blockIdx.x * 32;
    int m0 = blockIdx.y * 32;
    int tx = threadIdx.x, ty = threadIdx.y;
#pragma unroll
    for (int j = 0; j < 32; j += 8)
        tile[ty + j][tx] = x[(b * LEN + l0 + ty + j) * DM + m0 + tx];
    __syncthreads();
#pragma unroll
    for (int j = 0; j < 32; j += 8)
        g_xt[(b * DM + m0 + ty + j) * LEN + l0 + tx] = tile[tx][ty + j];
}

// -------- 2) Psum[k,l] = sum_{m'} exp(dt[m'] * Lam[k] * l) --------
__global__ void psum_kernel(const float* __restrict__ Lam,
                            const float* __restrict__ log_dt) {
    __shared__ float dt_s[DM];
    int k = blockIdx.x;
    int l = blockIdx.y * 128 + threadIdx.x;
    dt_s[threadIdx.x] = __expf(log_dt[threadIdx.x]);
    __syncthreads();
    float a = Lam[k] * (float)l;   // <= 0
    float s = 0.f;
#pragma unroll 8
    for (int mp = 0; mp < DM; ++mp)
        s += __expf(dt_s[mp] * a);
    g_psum[k * LEN + l] = s;
}

// -------- 3) G = C @ B --------
__global__ void gmat_kernel(const float* __restrict__ Bm,
                            const float* __restrict__ Cm) {
    __shared__ float c_s[DS];
    int m = blockIdx.x;
    int k = threadIdx.x;
    c_s[k] = Cm[m * DS + k];
    __syncthreads();
    float g = 0.f;
#pragma unroll 8
    for (int i = 0; i < DS; ++i)
        g = fmaf(c_s[i], Bm[i * DM + k], g);
    g_G[m * DS + k] = g;
}

// -------- 4) kernel[m,l] = sum_k G[m,k] * Psum[k,l] --------
// Reverted to the proven high-occupancy version (4096 CTAs, 23us).
__global__ void kern_kernel() {
    __shared__ float gs[DS];
    int m = blockIdx.x;
    int l = blockIdx.y * 128 + threadIdx.x;
    gs[threadIdx.x] = g_G[m * DS + threadIdx.x];
    __syncthreads();
    float s = 0.f;
#pragma unroll 8
    for (int k = 0; k < DS; ++k)
        s = fmaf(gs[k], g_psum[k * LEN + l], s);
    g_kern[m * LEN + l] = s;
}

// -------- 5) causal conv + skip, f32x2 packed FMA (R5 inner, 4 warps) ----
// 1D grid of 512: tt = 3 - (bid & 3) interleaves tile weights, m = bid >> 2.
// 128 threads; each owns 8 output rows x 8 batches (4 f32x2 accs per row).
// kv: LDS.32 (consecutive lanes, 1 crossbar phase) + MOV dup;
// xv: LDS.64 broadcast from pad-10 x tile. Per warp-tap: FMA 16 SM-cyc >
// crossbar 12 > issue 13 -> FMA-pipe bound on all 4 SMSPs.
__global__ void __launch_bounds__(NT) conv_kernel(const float* __restrict__ Dv,
                                                  float* __restrict__ out) {
    __shared__ __align__(16) float k_s[TO + TU];   // 1152 floats
    __shared__ __align__(16) float x_s[TU * 10];   // pad 10 -> aligned pairs

    const int bid = blockIdx.x;
    const int tt  = 3 - (bid & 3);
    const int m   = bid >> 2;
    const int t0  = tt * TO;
    const int tid = threadIdx.x;

    u64 acc[RR][4];
#pragma unroll
    for (int r = 0; r < RR; ++r)
#pragma unroll
        for (int h = 0; h < 4; ++h) acc[r][h] = 0ull;

    const float* krow = g_kern + m * LEN;
    const int n_u = (t0 + TO) / TU;

    for (int ut = 0; ut < n_u; ++ut) {
        const int u0 = ut * TU;
        __syncthreads();
        const int j0 = t0 - u0 - (TU - 1);
#pragma unroll
        for (int ii = 0; ii < (TO + TU) / NT; ++ii) {   // 9
            int i = tid + ii * NT;
            int j = j0 + i;
            k_s[i] = (j >= 0) ? krow[j] : 0.f;
        }
        {
            const float* xp = g_xt + m * LEN + u0 + tid;
#pragma unroll
            for (int b = 0; b < BSZ; ++b)
                x_s[tid * 10 + b] = xp[b * DM * LEN];
        }
        __syncthreads();

#pragma unroll 2
        for (int uj = 0; uj < TU; ++uj) {
            u64 xv[4];
            const float2* xp2 = (const float2*)(x_s + uj * 10);
#pragma unroll
            for (int h = 0; h < 4; ++h) {
                float2 v = xp2[h];
                xv[h] = pack2(v.x, v.y);
            }
#pragma unroll
            for (int r = 0; r < RR; ++r) {
                float kf = k_s[tid + r * NT + (TU - 1) - uj];
                u64 kv = pack2(kf, kf);
#pragma unroll
                for (int h = 0; h < 4; ++h)
                    ffma2(acc[r][h], kv, xv[h]);
            }
        }
    }

    // epilogue: skip connection + store to (b, l, m)
    const float dv = Dv[m];
#pragma unroll
    for (int r = 0; r < RR; ++r) {
        int l = t0 + tid + r * NT;
#pragma unroll
        for (int h = 0; h < 4; ++h) {
            float lo, hi;
            unpack2(acc[r][h], lo, hi);
            int b0 = 2 * h, b1 = 2 * h + 1;
            float x0 = g_xt[(b0 * DM + m) * LEN + l];
            float x1 = g_xt[(b1 * DM + m) * LEN + l];
            out[(b0 * LEN + l) * DM + m] = fmaf(dv, x0, lo);
            out[(b1 * LEN + l) * DM + m] = fmaf(dv, x1, hi);
        }
    }
}

extern "C" void kernel_launch(void* const* d_in, const int* in_sizes, int n_in,
                              void* d_out, int out_size) {
    const float* x      = (const float*)d_in[0];  // (8, 4096, 128)
    const float* Lam    = (const float*)d_in[1];  // (128,)
    const float* Bm     = (const float*)d_in[2];  // (128, 128)
    const float* Cm     = (const float*)d_in[3];  // (128, 128)
    const float* Dv     = (const float*)d_in[4];  // (128,)
    const float* log_dt = (const float*)d_in[5];  // (128,)
    float* out = (float*)d_out;

    transpose_kernel<<<dim3(LEN / 32, DM / 32, BSZ), dim3(32, 8)>>>(x);
    psum_kernel<<<dim3(DS, LEN / 128), 128>>>(Lam, log_dt);
    gmat_kernel<<<DM, DS>>>(Bm, Cm);
    kern_kernel<<<dim3(DM, LEN / 128), 128>>>();
    conv_kernel<<<(LEN / TO) * DM, NT>>>(Dv, out);
}

// round 9
// speedup vs baseline: 1.4955x; 1.4955x over previous
#include <cuda_runtime.h>
#include <cuda_bf16.h>

#define BSZ 8
#define LEN 4096
#define DM  128   // d_model (M)
#define DS  128   // d_state (N)

#define TO 512    // output tile (time) per CTA
#define TU 128    // input tile (time)
#define NT 64     // threads per CTA (conv)  -- proven best config
#define RR 8      // output rows (l = t0 + tid + r*64) per thread

// -------- scratch (__device__ globals; no allocation allowed) --------
__device__ float g_xt[BSZ * DM * LEN];    // x transposed to (b, m, l)
__device__ float g_psum[DS * LEN];        // Psum[k, l]
__device__ float g_kern[DM * LEN];        // kernel[m, l]
__device__ float g_G[DM * DS];            // G = C @ B

using u64 = unsigned long long;
__device__ __forceinline__ void ffma2(u64 &d, u64 a, u64 b) {
    asm("fma.rn.f32x2 %0, %1, %2, %0;" : "+l"(d) : "l"(a), "l"(b));
}
__device__ __forceinline__ u64 pack2(float lo, float hi) {
    u64 r; asm("mov.b64 %0, {%1, %2};" : "=l"(r) : "f"(lo), "f"(hi)); return r;
}
__device__ __forceinline__ void unpack2(u64 v, float &lo, float &hi) {
    asm("mov.b64 {%0, %1}, %2;" : "=f"(lo), "=f"(hi) : "l"(v));
}

// -------- 1) transpose x (b,l,m) -> (b,m,l) --------
__global__ void transpose_kernel(const float* __restrict__ x) {
    __shared__ float tile[32][33];
    int b  = blockIdx.z;
    int l0 = blockIdx.x * 32;
    int m0 = blockIdx.y * 32;
    int tx = threadIdx.x, ty = threadIdx.y;
#pragma unroll
    for (int j = 0; j < 32; j += 8)
        tile[ty + j][tx] = x[(b * LEN + l0 + ty + j) * DM + m0 + tx];
    __syncthreads();
#pragma unroll
    for (int j = 0; j < 32; j += 8)
        g_xt[(b * DM + m0 + ty + j) * LEN + l0 + tx] = tile[tx][ty + j];
}

// -------- 2) Psum[k,l] = sum_{m'} exp(dt[m'] * Lam[k] * l) --------
__global__ void psum_kernel(const float* __restrict__ Lam,
                            const float* __restrict__ log_dt) {
    __shared__ float dt_s[DM];
    int k = blockIdx.x;
    int l = blockIdx.y * 128 + threadIdx.x;
    dt_s[threadIdx.x] = __expf(log_dt[threadIdx.x]);
    __syncthreads();
    float a = Lam[k] * (float)l;   // <= 0
    float s = 0.f;
#pragma unroll 8
    for (int mp = 0; mp < DM; ++mp)
        s += __expf(dt_s[mp] * a);
    g_psum[k * LEN + l] = s;
}

// -------- 3) G = C @ B --------
__global__ void gmat_kernel(const float* __restrict__ Bm,
                            const float* __restrict__ Cm) {
    __shared__ float c_s[DS];
    int m = blockIdx.x;
    int k = threadIdx.x;
    c_s[k] = Cm[m * DS + k];
    __syncthreads();
    float g = 0.f;
#pragma unroll 8
    for (int i = 0; i < DS; ++i)
        g = fmaf(c_s[i], Bm[i * DM + k], g);
    g_G[m * DS + k] = g;
}

// -------- 4) kernel[m,l] = sum_k G[m,k] * Psum[k,l] (proven 23us) --------
__global__ void kern_kernel() {
    __shared__ float gs[DS];
    int m = blockIdx.x;
    int l = blockIdx.y * 128 + threadIdx.x;
    gs[threadIdx.x] = g_G[m * DS + threadIdx.x];
    __syncthreads();
    float s = 0.f;
#pragma unroll 8
    for (int k = 0; k < DS; ++k)
        s = fmaf(gs[k], g_psum[k * LEN + l], s);
    g_kern[m * LEN + l] = s;
}

// -------- 5) causal conv + skip (R5 inner loop; k resident + x dbl-buffer) --
// grid 1024: tt = 7 - (bid>>7) heavy-first, m = bid & 127.
// k_s: zero pad [0,TO) then krow[0..t0+TO) loaded ONCE (float4).
// x: register-prefetch next tile during compute; one barrier per tile.
__global__ void __launch_bounds__(NT) conv_kernel(const float* __restrict__ Dv,
                                                  float* __restrict__ out) {
    __shared__ __align__(16) float k_s[TO + LEN];   // 18.4KB used up to TO+t0+TO
    __shared__ __align__(16) float x_s[2][TU * 10]; // 10.25KB, pad-10 rows

    const int bid = blockIdx.x;
    const int tt  = (LEN / TO - 1) - (bid >> 7);    // 7..0, heavy first
    const int m   = bid & (DM - 1);
    const int t0  = tt * TO;
    const int tid = threadIdx.x;
    const int kmax = t0 + TO;

    u64 acc[RR][4];
#pragma unroll
    for (int r = 0; r < RR; ++r)
#pragma unroll
        for (int h = 0; h < 4; ++h) acc[r][h] = 0ull;

    const float* krow = g_kern + m * LEN;
    const float* xrow = g_xt + m * LEN;
    const int n_u = kmax / TU;

    // one-time k load: zero pad + data (both float4, coalesced)
    for (int i = tid * 4; i < TO; i += NT * 4)
        *(float4*)(k_s + i) = make_float4(0.f, 0.f, 0.f, 0.f);
    for (int i = tid * 4; i < kmax; i += NT * 4)
        *(float4*)(k_s + TO + i) = *(const float4*)(krow + i);

    // prefetch x tile 0 into registers, stage into buffer 0
    float xr[2][BSZ];
#pragma unroll
    for (int q = 0; q < 2; ++q)
#pragma unroll
        for (int b = 0; b < BSZ; ++b)
            xr[q][b] = xrow[b * DM * LEN + q * NT + tid];
#pragma unroll
    for (int q = 0; q < 2; ++q)
#pragma unroll
        for (int b = 0; b < BSZ; ++b)
            x_s[0][(q * NT + tid) * 10 + b] = xr[q][b];
    __syncthreads();

    for (int ut = 0; ut < n_u; ++ut) {
        const int cur = ut & 1;
        // issue next tile's LDGs (latency hidden under compute below)
        if (ut + 1 < n_u) {
            const int u0n = (ut + 1) * TU;
#pragma unroll
            for (int q = 0; q < 2; ++q)
#pragma unroll
                for (int b = 0; b < BSZ; ++b)
                    xr[q][b] = xrow[b * DM * LEN + u0n + q * NT + tid];
        }

        // compute: kbase indexes k_s with TO offset absorbing negative taps
        const int kbase = TO + t0 + tid - ut * TU;
#pragma unroll 2
        for (int uj = 0; uj < TU; ++uj) {
            u64 xv[4];
            const float2* xp2 = (const float2*)(x_s[cur] + uj * 10);
#pragma unroll
            for (int h = 0; h < 4; ++h) {
                float2 v = xp2[h];
                xv[h] = pack2(v.x, v.y);
            }
#pragma unroll
            for (int r = 0; r < RR; ++r) {
                float kf = k_s[kbase + r * NT - uj];
                u64 kv = pack2(kf, kf);
#pragma unroll
                for (int h = 0; h < 4; ++h)
                    ffma2(acc[r][h], kv, xv[h]);
            }
        }

        if (ut + 1 < n_u) {
#pragma unroll
            for (int q = 0; q < 2; ++q)
#pragma unroll
                for (int b = 0; b < BSZ; ++b)
                    x_s[cur ^ 1][(q * NT + tid) * 10 + b] = xr[q][b];
        }
        __syncthreads();
    }

    // epilogue: skip connection + store to (b, l, m)
    const float dv = Dv[m];
#pragma unroll
    for (int r = 0; r < RR; ++r) {
        int l = t0 + tid + r * NT;
#pragma unroll
        for (int h = 0; h < 4; ++h) {
            float lo, hi;
            unpack2(acc[r][h], lo, hi);
            int b0 = 2 * h, b1 = 2 * h + 1;
            float x0 = xrow[b0 * DM * LEN + l];
            float x1 = xrow[b1 * DM * LEN + l];
            out[(b0 * LEN + l) * DM + m] = fmaf(dv, x0, lo);
            out[(b1 * LEN + l) * DM + m] = fmaf(dv, x1, hi);
        }
    }
}

extern "C" void kernel_launch(void* const* d_in, const int* in_sizes, int n_in,
                              void* d_out, int out_size) {
    const float* x      = (const float*)d_in[0];  // (8, 4096, 128)
    const float* Lam    = (const float*)d_in[1];  // (128,)
    const float* Bm     = (const float*)d_in[2];  // (128, 128)
    const float* Cm     = (const float*)d_in[3];  // (128, 128)
    const float* Dv     = (const float*)d_in[4];  // (128,)
    const float* log_dt = (const float*)d_in[5];  // (128,)
    float* out = (float*)d_out;

    transpose_kernel<<<dim3(LEN / 32, DM / 32, BSZ), dim3(32, 8)>>>(x);
    psum_kernel<<<dim3(DS, LEN / 128), 128>>>(Lam, log_dt);
    gmat_kernel<<<DM, DS>>>(Bm, Cm);
    kern_kernel<<<dim3(DM, LEN / 128), 128>>>();
    conv_kernel<<<(LEN / TO) * DM, NT>>>(Dv, out);
}

// round 11
// speedup vs baseline: 2.6281x; 1.7573x over previous
#include <cuda_runtime.h>
#include <cuda_bf16.h>
#include <cstdint>

#define BSZ 8
#define LEN 4096
#define DM  128
#define DS  128
#define S   128          // time block
#define NB  32           // LEN/S

// -------- scratch (__device__ globals; no allocation allowed) --------
__device__ float g_xt[BSZ * DM * LEN];    // x transposed to (b, m, l)
__device__ float g_psum[DS * LEN];
__device__ float g_kern[DM * LEN];
__device__ float g_G[DM * DS];
__device__ float g_y[DM * BSZ * LEN];     // conv result, (m, b, l)

__device__ __forceinline__ uint32_t bf2_pack(float a, float b) {
    __nv_bfloat162 t = __floats2bfloat162_rn(a, b);   // a -> low, b -> high
    return *reinterpret_cast<uint32_t*>(&t);
}
__device__ __forceinline__ void hl_split(float v, float& h, float& l) {
    __nv_bfloat16 hb = __float2bfloat16(v);
    h = __bfloat162float(hb);
    l = v - h;
}

// m16n8k16 row.col f32.bf16.bf16.f32 (legacy HMMA, valid on compute_103 base)
__device__ __forceinline__ void mma16816(float* c, const uint32_t* a,
                                         const uint32_t* b) {
    asm volatile(
        "mma.sync.aligned.m16n8k16.row.col.f32.bf16.bf16.f32 "
        "{%0,%1,%2,%3}, {%4,%5,%6,%7}, {%8,%9}, {%0,%1,%2,%3};"
        : "+f"(c[0]), "+f"(c[1]), "+f"(c[2]), "+f"(c[3])
        : "r"(a[0]), "r"(a[1]), "r"(a[2]), "r"(a[3]), "r"(b[0]), "r"(b[1]));
}

// ======================= prologue kernels (proven) =======================
__global__ void transpose_kernel(const float* __restrict__ x) {
    __shared__ float tile[32][33];
    int b  = blockIdx.z;
    int l0 = blockIdx.x * 32;
    int m0 = blockIdx.y * 32;
    int tx = threadIdx.x, ty = threadIdx.y;
#pragma unroll
    for (int j = 0; j < 32; j += 8)
        tile[ty + j][tx] = x[(b * LEN + l0 + ty + j) * DM + m0 + tx];
    __syncthreads();
#pragma unroll
    for (int j = 0; j < 32; j += 8)
        g_xt[(b * DM + m0 + ty + j) * LEN + l0 + tx] = tile[tx][ty + j];
}

__global__ void psum_kernel(const float* __restrict__ Lam,
                            const float* __restrict__ log_dt) {
    __shared__ float dt_s[DM];
    int k = blockIdx.x;
    int l = blockIdx.y * 128 + threadIdx.x;
    dt_s[threadIdx.x] = __expf(log_dt[threadIdx.x]);
    __syncthreads();
    float a = Lam[k] * (float)l;
    float s = 0.f;
#pragma unroll 8
    for (int mp = 0; mp < DM; ++mp)
        s += __expf(dt_s[mp] * a);
    g_psum[k * LEN + l] = s;
}

__global__ void gmat_kernel(const float* __restrict__ Bm,
                            const float* __restrict__ Cm) {
    __shared__ float c_s[DS];
    int m = blockIdx.x;
    int k = threadIdx.x;
    c_s[k] = Cm[m * DS + k];
    __syncthreads();
    float g = 0.f;
#pragma unroll 8
    for (int i = 0; i < DS; ++i)
        g = fmaf(c_s[i], Bm[i * DM + k], g);
    g_G[m * DS + k] = g;
}

__global__ void kern_kernel() {
    __shared__ float gs[DS];
    int m = blockIdx.x;
    int l = blockIdx.y * 128 + threadIdx.x;
    gs[threadIdx.x] = g_G[m * DS + threadIdx.x];
    __syncthreads();
    float s = 0.f;
#pragma unroll 8
    for (int k = 0; k < DS; ++k)
        s = fmaf(gs[k], g_psum[k * LEN + l], s);
    g_kern[m * LEN + l] = s;
}

// ======================= tensor-core conv (mma.sync HMMA) =======================
// Per CTA (one m): Y[i, nb] (128 x 256), nb = 8*j + b.
//   Y[:, 8j+b] = sum_{d<=j} T_d(128x128) @ X[:, 8(j-d)+b]
// A[i,u] = k[d*128 + i - u]  -> fragment regs come straight from a
// paired-descending kernel array kp[c] = (bf16 k[c], bf16 k[c-1]).
// bf16 hi/lo split, 3 products: Ah*Bh + Ah*Bl + Al*Bh (drop lo*lo ~2^-18).
// Warp w owns n8-column tiles s in {w, w+8, w+16, w+24} (interleaved balance).
#define XSTRIDE 68                        // u32 row stride -> conflict-free
#define KPOFF   136
#define KPSZ    4240
#define SM_CONV ((2 * 256 * XSTRIDE + 2 * KPSZ) * 4)   // 173184 B

__global__ void __launch_bounds__(256, 1) conv_mma_kernel() {
    extern __shared__ char smem[];
    uint32_t* XH  = (uint32_t*)smem;             // [256][68]
    uint32_t* XL  = XH + 256 * XSTRIDE;
    uint32_t* KPH = XL + 256 * XSTRIDE;          // logical index c+KPOFF
    uint32_t* KPL = KPH + KPSZ;

    const int tid = threadIdx.x;
    const int m   = blockIdx.x;

    // ---- fill kp arrays (reversed-pair kernel, hi/lo) ----
    const float* krow = g_kern + m * LEN;
    for (int i = tid; i < KPSZ; i += 256) {
        int c = i - KPOFF;
        float f0 = (c >= 0 && c < LEN) ? krow[c] : 0.f;
        float f1 = (c >= 1 && c <= LEN) ? krow[c - 1] : 0.f;
        float h0, l0, h1, l1;
        hl_split(f0, h0, l0); hl_split(f1, h1, l1);
        KPH[i] = bf2_pack(h0, h1);
        KPL[i] = bf2_pack(l0, l1);
    }
    // ---- fill X (nb-major, pairs along u), hi/lo ----
    for (int idx = tid; idx < 256 * 64; idx += 256) {
        int nb = idx >> 6, qq = idx & 63;
        int b = nb & 7, j = nb >> 3;
        float2 v = *(const float2*)(g_xt + (size_t)(b * DM + m) * LEN + j * S + 2 * qq);
        float h0, l0, h1, l1;
        hl_split(v.x, h0, l0); hl_split(v.y, h1, l1);
        XH[nb * XSTRIDE + qq] = bf2_pack(h0, h1);
        XL[nb * XSTRIDE + qq] = bf2_pack(l0, l1);
    }
    __syncthreads();

    const int w    = tid >> 5;
    const int lane = tid & 31;
    const int gq   = lane >> 2;     // group row
    const int tq   = lane & 3;      // thread in group

    float acc[8][4][4];             // [mt][slot][reg]
#pragma unroll
    for (int mt = 0; mt < 8; ++mt)
#pragma unroll
        for (int si = 0; si < 4; ++si)
#pragma unroll
            for (int r = 0; r < 4; ++r) acc[mt][si][r] = 0.f;

    const int dmax = w + 24;        // largest s this warp owns
    for (int d = 0; d <= dmax; ++d) {
        for (int ks = 0; ks < 8; ++ks) {
            const int u0 = 16 * ks;
            // B fragments for the warp's valid column tiles
            uint32_t bh[4][2], bl[4][2];
#pragma unroll
            for (int si = 0; si < 4; ++si) {
                int s = w + 8 * si;
                if (s >= d) {
                    int xi = (8 * (s - d) + gq) * XSTRIDE + 8 * ks + tq;
                    bh[si][0] = XH[xi]; bh[si][1] = XH[xi + 4];
                    bl[si][0] = XL[xi]; bl[si][1] = XL[xi + 4];
                }
            }
            // rolling A fragments across m-tiles
            const int C0 = d * S + gq - 2 * tq - u0 + KPOFF;
            uint32_t ahm = KPH[C0 - 8], ah0 = KPH[C0], ahp = KPH[C0 + 8];
            uint32_t alm = KPL[C0 - 8], al0 = KPL[C0], alp = KPL[C0 + 8];
#pragma unroll
            for (int mt = 0; mt < 8; ++mt) {
                uint32_t ah[4] = {ah0, ahp, ahm, ah0};
                uint32_t al[4] = {al0, alp, alm, al0};
#pragma unroll
                for (int si = 0; si < 4; ++si) {
                    int s = w + 8 * si;
                    if (s >= d) {
                        mma16816(acc[mt][si], ah, bh[si]);
                        mma16816(acc[mt][si], ah, bl[si]);
                        mma16816(acc[mt][si], al, bh[si]);
                    }
                }
                if (mt < 7) {
                    int Cn = C0 + 16 * (mt + 1);
                    ahm = ahp; ah0 = KPH[Cn]; ahp = KPH[Cn + 8];
                    alm = alp; al0 = KPL[Cn]; alp = KPL[Cn + 8];
                }
            }
        }
    }

    // ---- epilogue: C frags -> g_y (m, b, l) ----
#pragma unroll
    for (int mt = 0; mt < 8; ++mt)
#pragma unroll
        for (int si = 0; si < 4; ++si) {
            int s = w + 8 * si;
            int l = S * s + 16 * mt + gq;
            size_t b0 = (size_t)(m * 8 + 2 * tq) * LEN;
            size_t b1 = (size_t)(m * 8 + 2 * tq + 1) * LEN;
            g_y[b0 + l]     = acc[mt][si][0];
            g_y[b1 + l]     = acc[mt][si][1];
            g_y[b0 + l + 8] = acc[mt][si][2];
            g_y[b1 + l + 8] = acc[mt][si][3];
        }
}

// ======================= epilogue: transpose + skip =======================
__global__ void ytrans_kernel(const float* __restrict__ Dv,
                              float* __restrict__ out) {
    __shared__ float tile[32][33];
    int b  = blockIdx.z;
    int l0 = blockIdx.x * 32;
    int m0 = blockIdx.y * 32;
    int tx = threadIdx.x, ty = threadIdx.y;
#pragma unroll
    for (int j = 0; j < 32; j += 8) {
        int mm = m0 + ty + j;
        float y  = g_y[(size_t)(mm * 8 + b) * LEN + l0 + tx];
        float xv = g_xt[(size_t)(b * DM + mm) * LEN + l0 + tx];
        tile[ty + j][tx] = fmaf(Dv[mm], xv, y);
    }
    __syncthreads();
#pragma unroll
    for (int j = 0; j < 32; j += 8)
        out[(size_t)(b * LEN + l0 + ty + j) * DM + m0 + tx] = tile[tx][ty + j];
}

extern "C" void kernel_launch(void* const* d_in, const int* in_sizes, int n_in,
                              void* d_out, int out_size) {
    const float* x      = (const float*)d_in[0];  // (8, 4096, 128)
    const float* Lam    = (const float*)d_in[1];
    const float* Bm     = (const float*)d_in[2];
    const float* Cm     = (const float*)d_in[3];
    const float* Dv     = (const float*)d_in[4];
    const float* log_dt = (const float*)d_in[5];
    float* out = (float*)d_out;

    cudaFuncSetAttribute(conv_mma_kernel,
                         cudaFuncAttributeMaxDynamicSharedMemorySize, SM_CONV);

    transpose_kernel<<<dim3(LEN / 32, DM / 32, BSZ), dim3(32, 8)>>>(x);
    psum_kernel<<<dim3(DS, LEN / 128), 128>>>(Lam, log_dt);
    gmat_kernel<<<DM, DS>>>(Bm, Cm);
    kern_kernel<<<dim3(DM, LEN / 128), 128>>>();
    conv_mma_kernel<<<DM, 256, SM_CONV>>>();
    ytrans_kernel<<<dim3(LEN / 32, DM / 32, BSZ), dim3(32, 8)>>>(Dv, out);
}

// round 12
// speedup vs baseline: 3.6908x; 1.4044x over previous
#include <cuda_runtime.h>
#include <cuda_bf16.h>
#include <cuda_fp16.h>
#include <cstdint>

#define BSZ 8
#define LEN 4096
#define DM  128
#define DS  128
#define S   128          // time block
#define NB  32           // LEN/S

// -------- scratch (__device__ globals; no allocation allowed) --------
__device__ float g_xt[BSZ * DM * LEN];    // x transposed to (b, m, l)
__device__ float g_psum[DS * LEN];
__device__ float g_kern[DM * LEN];
__device__ float g_G[DM * DS];
__device__ float g_y[DM * BSZ * LEN];     // conv result, (m, b, l)

__device__ __forceinline__ uint32_t h2_pack(float a, float b) {
    __half2 t = __floats2half2_rn(a, b);   // a -> low, b -> high
    return *reinterpret_cast<uint32_t*>(&t);
}
__device__ __forceinline__ void hl_split_h(float v, float& h, float& l) {
    __half hb = __float2half_rn(v);
    h = __half2float(hb);
    l = v - h;
}

// m16n8k16 row.col f32.f16.f16.f32 (legacy HMMA, valid on compute_103 base)
__device__ __forceinline__ void mma16816(float* c, const uint32_t* a,
                                         const uint32_t* b) {
    asm volatile(
        "mma.sync.aligned.m16n8k16.row.col.f32.f16.f16.f32 "
        "{%0,%1,%2,%3}, {%4,%5,%6,%7}, {%8,%9}, {%0,%1,%2,%3};"
        : "+f"(c[0]), "+f"(c[1]), "+f"(c[2]), "+f"(c[3])
        : "r"(a[0]), "r"(a[1]), "r"(a[2]), "r"(a[3]), "r"(b[0]), "r"(b[1]));
}

// ======================= prologue kernels (proven) =======================
__global__ void transpose_kernel(const float* __restrict__ x) {
    __shared__ float tile[32][33];
    int b  = blockIdx.z;
    int l0 = blockIdx.x * 32;
    int m0 = blockIdx.y * 32;
    int tx = threadIdx.x, ty = threadIdx.y;
#pragma unroll
    for (int j = 0; j < 32; j += 8)
        tile[ty + j][tx] = x[(b * LEN + l0 + ty + j) * DM + m0 + tx];
    __syncthreads();
#pragma unroll
    for (int j = 0; j < 32; j += 8)
        g_xt[(b * DM + m0 + ty + j) * LEN + l0 + tx] = tile[tx][ty + j];
}

__global__ void psum_kernel(const float* __restrict__ Lam,
                            const float* __restrict__ log_dt) {
    __shared__ float dt_s[DM];
    int k = blockIdx.x;
    int l = blockIdx.y * 128 + threadIdx.x;
    dt_s[threadIdx.x] = __expf(log_dt[threadIdx.x]);
    __syncthreads();
    float a = Lam[k] * (float)l;
    float s = 0.f;
#pragma unroll 8
    for (int mp = 0; mp < DM; ++mp)
        s += __expf(dt_s[mp] * a);
    g_psum[k * LEN + l] = s;
}

__global__ void gmat_kernel(const float* __restrict__ Bm,
                            const float* __restrict__ Cm) {
    __shared__ float c_s[DS];
    int m = blockIdx.x;
    int k = threadIdx.x;
    c_s[k] = Cm[m * DS + k];
    __syncthreads();
    float g = 0.f;
#pragma unroll 8
    for (int i = 0; i < DS; ++i)
        g = fmaf(c_s[i], Bm[i * DM + k], g);
    g_G[m * DS + k] = g;
}

__global__ void kern_kernel() {
    __shared__ float gs[DS];
    int m = blockIdx.x;
    int l = blockIdx.y * 128 + threadIdx.x;
    gs[threadIdx.x] = g_G[m * DS + threadIdx.x];
    __syncthreads();
    float s = 0.f;
#pragma unroll 8
    for (int k = 0; k < DS; ++k)
        s = fmaf(gs[k], g_psum[k * LEN + l], s);
    g_kern[m * LEN + l] = s;
}

// ======================= tensor-core conv (mma.sync HMMA, fp16) ============
// Per CTA (one m): Y[i, nb] (128 x 256), nb = 8*j + b.
//   Y[:, 8j+b] = sum_{d<=j} T_d(128x128) @ X[:, 8(j-d)+b]
// fp16 hi/lo split of X only for the correction; K kept in fp16 hi (the
// dropped K_lo*X term is ~2^-12 relative, random-sign -> ~1e-4 norm error):
//   Y ~= Kh*Xh + Kh*Xl           (2 products per tile)
// Warp w owns n8-column tiles {w, 15-w, 16+w, 31-w} (equal work = 66/warp).
#define XSTRIDE 68                        // u32 row stride -> conflict-free
#define KPOFF   136
#define KPSZ    4240
#define SM_CONV ((2 * 256 * XSTRIDE + KPSZ) * 4)   // 156224 B

__global__ void __launch_bounds__(256, 1) conv_mma_kernel() {
    extern __shared__ char smem[];
    uint32_t* XH  = (uint32_t*)smem;             // [256][68]
    uint32_t* XL  = XH + 256 * XSTRIDE;
    uint32_t* KPH = XL + 256 * XSTRIDE;          // logical index c+KPOFF

    const int tid = threadIdx.x;
    const int m   = blockIdx.x;

    // ---- fill kp array (reversed-pair kernel, fp16 hi only) ----
    const float* krow = g_kern + m * LEN;
    for (int i = tid; i < KPSZ; i += 256) {
        int c = i - KPOFF;
        float f0 = (c >= 0 && c < LEN) ? krow[c] : 0.f;
        float f1 = (c >= 1 && c <= LEN) ? krow[c - 1] : 0.f;
        KPH[i] = h2_pack(f0, f1);   // rn-rounded to fp16 = K_hi
    }
    // ---- fill X (nb-major, pairs along u), fp16 hi/lo ----
    for (int idx = tid; idx < 256 * 64; idx += 256) {
        int nb = idx >> 6, qq = idx & 63;
        int b = nb & 7, j = nb >> 3;
        float2 v = *(const float2*)(g_xt + (size_t)(b * DM + m) * LEN + j * S + 2 * qq);
        float h0, l0, h1, l1;
        hl_split_h(v.x, h0, l0); hl_split_h(v.y, h1, l1);
        XH[nb * XSTRIDE + qq] = h2_pack(h0, h1);
        XL[nb * XSTRIDE + qq] = h2_pack(l0, l1);
    }
    __syncthreads();

    const int w    = tid >> 5;
    const int lane = tid & 31;
    const int gq   = lane >> 2;     // group row
    const int tq   = lane & 3;      // thread in group

    const int sTab[4] = {w, 15 - w, 16 + w, 31 - w};   // balanced slots

    float acc[8][4][4];             // [mt][slot][reg]
#pragma unroll
    for (int mt = 0; mt < 8; ++mt)
#pragma unroll
        for (int si = 0; si < 4; ++si)
#pragma unroll
            for (int r = 0; r < 4; ++r) acc[mt][si][r] = 0.f;

    const int dmax = 31 - w;        // largest s this warp owns
    for (int d = 0; d <= dmax; ++d) {
        for (int ks = 0; ks < 8; ++ks) {
            const int u0 = 16 * ks;
            // B fragments for the warp's valid column tiles
            uint32_t bh[4][2], bl[4][2];
#pragma unroll
            for (int si = 0; si < 4; ++si) {
                int s = sTab[si];
                if (s >= d) {
                    int xi = (8 * (s - d) + gq) * XSTRIDE + 8 * ks + tq;
                    bh[si][0] = XH[xi]; bh[si][1] = XH[xi + 4];
                    bl[si][0] = XL[xi]; bl[si][1] = XL[xi + 4];
                }
            }
            // rolling A fragments (K hi only) across m-tiles
            const int C0 = d * S + gq - 2 * tq - u0 + KPOFF;
            uint32_t ahm = KPH[C0 - 8], ah0 = KPH[C0], ahp = KPH[C0 + 8];
#pragma unroll
            for (int mt = 0; mt < 8; ++mt) {
                uint32_t ah[4] = {ah0, ahp, ahm, ah0};
#pragma unroll
                for (int si = 0; si < 4; ++si) {
                    int s = sTab[si];
                    if (s >= d) {
                        mma16816(acc[mt][si], ah, bh[si]);
                        mma16816(acc[mt][si], ah, bl[si]);
                    }
                }
                if (mt < 7) {
                    int Cn = C0 + 16 * (mt + 1);
                    ahm = ahp; ah0 = KPH[Cn]; ahp = KPH[Cn + 8];
                }
            }
        }
    }

    // ---- epilogue: C frags -> g_y (m, b, l) ----
#pragma unroll
    for (int mt = 0; mt < 8; ++mt)
#pragma unroll
        for (int si = 0; si < 4; ++si) {
            int s = sTab[si];
            int l = S * s + 16 * mt + gq;
            size_t b0 = (size_t)(m * 8 + 2 * tq) * LEN;
            size_t b1 = (size_t)(m * 8 + 2 * tq + 1) * LEN;
            g_y[b0 + l]     = acc[mt][si][0];
            g_y[b1 + l]     = acc[mt][si][1];
            g_y[b0 + l + 8] = acc[mt][si][2];
            g_y[b1 + l + 8] = acc[mt][si][3];
        }
}

// ======================= epilogue: transpose + skip =======================
__global__ void ytrans_kernel(const float* __restrict__ Dv,
                              float* __restrict__ out) {
    __shared__ float tile[32][33];
    int b  = blockIdx.z;
    int l0 = blockIdx.x * 32;
    int m0 = blockIdx.y * 32;
    int tx = threadIdx.x, ty = threadIdx.y;
#pragma unroll
    for (int j = 0; j < 32; j += 8) {
        int mm = m0 + ty + j;
        float y  = g_y[(size_t)(mm * 8 + b) * LEN + l0 + tx];
        float xv = g_xt[(size_t)(b * DM + mm) * LEN + l0 + tx];
        tile[ty + j][tx] = fmaf(Dv[mm], xv, y);
    }
    __syncthreads();
#pragma unroll
    for (int j = 0; j < 32; j += 8)
        out[(size_t)(b * LEN + l0 + ty + j) * DM + m0 + tx] = tile[tx][ty + j];
}

extern "C" void kernel_launch(void* const* d_in, const int* in_sizes, int n_in,
                              void* d_out, int out_size) {
    const float* x      = (const float*)d_in[0];  // (8, 4096, 128)
    const float* Lam    = (const float*)d_in[1];
    const float* Bm     = (const float*)d_in[2];
    const float* Cm     = (const float*)d_in[3];
    const float* Dv     = (const float*)d_in[4];
    const float* log_dt = (const float*)d_in[5];
    float* out = (float*)d_out;

    cudaFuncSetAttribute(conv_mma_kernel,
                         cudaFuncAttributeMaxDynamicSharedMemorySize, SM_CONV);

    transpose_kernel<<<dim3(LEN / 32, DM / 32, BSZ), dim3(32, 8)>>>(x);
    psum_kernel<<<dim3(DS, LEN / 128), 128>>>(Lam, log_dt);
    gmat_kernel<<<DM, DS>>>(Bm, Cm);
    kern_kernel<<<dim3(DM, LEN / 128), 128>>>();
    conv_mma_kernel<<<DM, 256, SM_CONV>>>();
    ytrans_kernel<<<dim3(LEN / 32, DM / 32, BSZ), dim3(32, 8)>>>(Dv, out);
}

// round 13
// speedup vs baseline: 5.6950x; 1.5430x over previous
#include <cuda_runtime.h>
#include <cuda_bf16.h>
#include <cuda_fp16.h>
#include <cstdint>

#define BSZ 8
#define LEN 4096
#define DM  128
#define DS  128
#define S   128          // time block
#define NB  32           // LEN/S

// -------- scratch (__device__ globals; no allocation allowed) --------
__device__ float g_xt[BSZ * DM * LEN];    // x transposed to (b, m, l)
__device__ float g_kern[DM * LEN];
__device__ float g_G[DM * DS];
__device__ float g_y[DM * BSZ * LEN];     // conv result, (m, b, l)

__device__ __forceinline__ uint32_t h2_pack(float a, float b) {
    __half2 t = __floats2half2_rn(a, b);   // a -> low, b -> high
    return *reinterpret_cast<uint32_t*>(&t);
}

// m16n8k16 row.col f32.f16.f16.f32 (legacy HMMA, valid on compute_103 base)
__device__ __forceinline__ void mma16816(float* c, const uint32_t* a,
                                         const uint32_t* b) {
    asm volatile(
        "mma.sync.aligned.m16n8k16.row.col.f32.f16.f16.f32 "
        "{%0,%1,%2,%3}, {%4,%5,%6,%7}, {%8,%9}, {%0,%1,%2,%3};"
        : "+f"(c[0]), "+f"(c[1]), "+f"(c[2]), "+f"(c[3])
        : "r"(a[0]), "r"(a[1]), "r"(a[2]), "r"(a[3]), "r"(b[0]), "r"(b[1]));
}

// ======================= 1) transpose x (b,l,m) -> (b,m,l) =================
__global__ void transpose_kernel(const float* __restrict__ x) {
    __shared__ float tile[32][33];
    int b  = blockIdx.z;
    int l0 = blockIdx.x * 32;
    int m0 = blockIdx.y * 32;
    int tx = threadIdx.x, ty = threadIdx.y;
#pragma unroll
    for (int j = 0; j < 32; j += 8)
        tile[ty + j][tx] = x[(b * LEN + l0 + ty + j) * DM + m0 + tx];
    __syncthreads();
#pragma unroll
    for (int j = 0; j < 32; j += 8)
        g_xt[(b * DM + m0 + ty + j) * LEN + l0 + tx] = tile[tx][ty + j];
}

// ======================= 2) G = C @ B =====================================
__global__ void gmat_kernel(const float* __restrict__ Bm,
                            const float* __restrict__ Cm) {
    __shared__ float c_s[DS];
    int m = blockIdx.x;
    int k = threadIdx.x;
    c_s[k] = Cm[m * DS + k];
    __syncthreads();
    float g = 0.f;
#pragma unroll 8
    for (int i = 0; i < DS; ++i)
        g = fmaf(c_s[i], Bm[i * DM + k], g);
    g_G[m * DS + k] = g;
}

// ======================= 3) fused psum + kern ==============================
// grid 128 (one 32-l chunk each, full wave). Phase A: psum[k][l] in smem
// (MUFU-bound, spread over all CTAs). Phase B: kern[m,l] = G @ psum with
// G resident in smem (broadcast reads).
__global__ void __launch_bounds__(256) pk_kernel(const float* __restrict__ Lam,
                                                 const float* __restrict__ log_dt) {
    __shared__ float Gs[DM][DS];     // 64KB, [m][k]
    __shared__ float ps[DS][33];     // [k][l], pad 33
    __shared__ float dt_s[DM];
    const int tid = threadIdx.x;
    const int l0  = blockIdx.x * 32;

    if (tid < DM) dt_s[tid] = __expf(log_dt[tid]);
    for (int i = tid * 4; i < DM * DS; i += 256 * 4)
        *(float4*)(&Gs[0][0] + i) = *(const float4*)(g_G + i);
    __syncthreads();

    // Phase A: 128k x 32l entries, 16 per thread
    for (int e = tid; e < DS * 32; e += 256) {
        int k = e >> 5, l = e & 31;
        float a = Lam[k] * (float)(l0 + l);
        float s = 0.f;
#pragma unroll 8
        for (int mp = 0; mp < DM; ++mp)
            s += __expf(dt_s[mp] * a);
        ps[k][l] = s;
    }
    __syncthreads();

    // Phase B: thread -> (l = tid&31, m0 = (tid>>5)*16), 16 outputs
    const int l  = tid & 31;
    const int m0 = (tid >> 5) * 16;
    float acc[16];
#pragma unroll
    for (int i = 0; i < 16; ++i) acc[i] = 0.f;
#pragma unroll 4
    for (int k = 0; k < DS; ++k) {
        float p = ps[k][l];
#pragma unroll
        for (int i = 0; i < 16; ++i)
            acc[i] = fmaf(Gs[m0 + i][k], p, acc[i]);
    }
#pragma unroll
    for (int i = 0; i < 16; ++i)
        g_kern[(m0 + i) * LEN + l0 + l] = acc[i];
}

// ======================= 4) tensor-core conv (fp16 HMMA, 1 product) ========
// Per CTA (one m): Y[i, nb] (128 x 256), nb = 8*j + b.
//   Y[:, 8j+b] = sum_{d<=j} T_d(128x128) @ X[:, 8(j-d)+b]
// Single product Kh*Xh; dropped Klo*X (+ Kh*Xlo) ~ 2^-12 random-sign each
// -> rel_err ~3e-4 (measured 2.02e-4 with only Klo*X dropped).
// Warp w owns n8-column tiles {w, 15-w, 16+w, 31-w} (equal work = 66/warp).
#define XSTRIDE 68                        // u32 row stride -> conflict-free
#define KPOFF   136
#define KPSZ    4240
#define SM_CONV ((256 * XSTRIDE + KPSZ) * 4)   // 86592 B

__global__ void __launch_bounds__(256, 1) conv_mma_kernel() {
    extern __shared__ char smem[];
    uint32_t* XH  = (uint32_t*)smem;             // [256][68]
    uint32_t* KPH = XH + 256 * XSTRIDE;          // logical index c+KPOFF

    const int tid = threadIdx.x;
    const int m   = blockIdx.x;

    // ---- fill kp array (reversed-pair kernel, fp16) ----
    const float* krow = g_kern + m * LEN;
    for (int i = tid; i < KPSZ; i += 256) {
        int c = i - KPOFF;
        float f0 = (c >= 0 && c < LEN) ? krow[c] : 0.f;
        float f1 = (c >= 1 && c <= LEN) ? krow[c - 1] : 0.f;
        KPH[i] = h2_pack(f0, f1);
    }
    // ---- fill X (nb-major, pairs along u), fp16 ----
    for (int idx = tid; idx < 256 * 64; idx += 256) {
        int nb = idx >> 6, qq = idx & 63;
        int b = nb & 7, j = nb >> 3;
        float2 v = *(const float2*)(g_xt + (size_t)(b * DM + m) * LEN + j * S + 2 * qq);
        XH[nb * XSTRIDE + qq] = h2_pack(v.x, v.y);
    }
    __syncthreads();

    const int w    = tid >> 5;
    const int lane = tid & 31;
    const int gq   = lane >> 2;     // group row
    const int tq   = lane & 3;      // thread in group

    const int sTab[4] = {w, 15 - w, 16 + w, 31 - w};   // balanced slots

    float acc[8][4][4];             // [mt][slot][reg]
#pragma unroll
    for (int mt = 0; mt < 8; ++mt)
#pragma unroll
        for (int si = 0; si < 4; ++si)
#pragma unroll
            for (int r = 0; r < 4; ++r) acc[mt][si][r] = 0.f;

    const int dmax = 31 - w;        // largest s this warp owns
    for (int d = 0; d <= dmax; ++d) {
        for (int ks = 0; ks < 8; ++ks) {
            const int u0 = 16 * ks;
            // B fragments for the warp's valid column tiles
            uint32_t bh[4][2];
#pragma unroll
            for (int si = 0; si < 4; ++si) {
                int s = sTab[si];
                if (s >= d) {
                    int xi = (8 * (s - d) + gq) * XSTRIDE + 8 * ks + tq;
                    bh[si][0] = XH[xi]; bh[si][1] = XH[xi + 4];
                }
            }
            // rolling A fragments across m-tiles
            const int C0 = d * S + gq - 2 * tq - u0 + KPOFF;
            uint32_t ahm = KPH[C0 - 8], ah0 = KPH[C0], ahp = KPH[C0 + 8];
#pragma unroll
            for (int mt = 0; mt < 8; ++mt) {
                uint32_t ah[4] = {ah0, ahp, ahm, ah0};
#pragma unroll
                for (int si = 0; si < 4; ++si) {
                    int s = sTab[si];
                    if (s >= d)
                        mma16816(acc[mt][si], ah, bh[si]);
                }
                if (mt < 7) {
                    int Cn = C0 + 16 * (mt + 1);
                    ahm = ahp; ah0 = KPH[Cn]; ahp = KPH[Cn + 8];
                }
            }
        }
    }

    // ---- epilogue: C frags -> g_y (m, b, l) ----
#pragma unroll
    for (int mt = 0; mt < 8; ++mt)
#pragma unroll
        for (int si = 0; si < 4; ++si) {
            int s = sTab[si];
            int l = S * s + 16 * mt + gq;
            size_t b0 = (size_t)(m * 8 + 2 * tq) * LEN;
            size_t b1 = (size_t)(m * 8 + 2 * tq + 1) * LEN;
            g_y[b0 + l]     = acc[mt][si][0];
            g_y[b1 + l]     = acc[mt][si][1];
            g_y[b0 + l + 8] = acc[mt][si][2];
            g_y[b1 + l + 8] = acc[mt][si][3];
        }
}

// ======================= 5) epilogue: transpose + skip =====================
__global__ void ytrans_kernel(const float* __restrict__ Dv,
                              float* __restrict__ out) {
    __shared__ float tile[32][33];
    int b  = blockIdx.z;
    int l0 = blockIdx.x * 32;
    int m0 = blockIdx.y * 32;
    int tx = threadIdx.x, ty = threadIdx.y;
#pragma unroll
    for (int j = 0; j < 32; j += 8) {
        int mm = m0 + ty + j;
        float y  = g_y[(size_t)(mm * 8 + b) * LEN + l0 + tx];
        float xv = g_xt[(size_t)(b * DM + mm) * LEN + l0 + tx];
        tile[ty + j][tx] = fmaf(Dv[mm], xv, y);
    }
    __syncthreads();
#pragma unroll
    for (int j = 0; j < 32; j += 8)
        out[(size_t)(b * LEN + l0 + ty + j) * DM + m0 + tx] = tile[tx][ty + j];
}

extern "C" void kernel_launch(void* const* d_in, const int* in_sizes, int n_in,
                              void* d_out, int out_size) {
    const float* x      = (const float*)d_in[0];  // (8, 4096, 128)
    const float* Lam    = (const float*)d_in[1];
    const float* Bm     = (const float*)d_in[2];
    const float* Cm     = (const float*)d_in[3];
    const float* Dv     = (const float*)d_in[4];
    const float* log_dt = (const float*)d_in[5];
    float* out = (float*)d_out;

    cudaFuncSetAttribute(conv_mma_kernel,
                         cudaFuncAttributeMaxDynamicSharedMemorySize, SM_CONV);

    transpose_kernel<<<dim3(LEN / 32, DM / 32, BSZ), dim3(32, 8)>>>(x);
    gmat_kernel<<<DM, DS>>>(Bm, Cm);
    pk_kernel<<<LEN / 32, 256>>>(Lam, log_dt);
    conv_mma_kernel<<<DM, 256, SM_CONV>>>();
    ytrans_kernel<<<dim3(LEN / 32, DM / 32, BSZ), dim3(32, 8)>>>(Dv, out);
}

// round 14
// speedup vs baseline: 5.8869x; 1.0337x over previous
#include <cuda_runtime.h>
#include <cuda_bf16.h>
#include <cuda_fp16.h>
#include <cstdint>

#define BSZ 8
#define LEN 4096
#define DM  128
#define DS  128
#define S   128          // time block
#define NB  32           // LEN/S

// -------- scratch (__device__ globals; no allocation allowed) --------
__device__ float g_xt[BSZ * DM * LEN];    // x transposed to (b, m, l)
__device__ float g_kern[DM * LEN];
__device__ float g_G[DM * DS];
__device__ float g_y[DM * BSZ * LEN];     // conv result, (m, b, l)

__device__ __forceinline__ uint32_t h2_pack(float a, float b) {
    __half2 t = __floats2half2_rn(a, b);   // a -> low, b -> high
    return *reinterpret_cast<uint32_t*>(&t);
}

// m16n8k16 row.col f32.f16.f16.f32 (legacy HMMA, valid on compute_103 base)
__device__ __forceinline__ void mma16816(float* c, const uint32_t* a,
                                         const uint32_t* b) {
    asm volatile(
        "mma.sync.aligned.m16n8k16.row.col.f32.f16.f16.f32 "
        "{%0,%1,%2,%3}, {%4,%5,%6,%7}, {%8,%9}, {%0,%1,%2,%3};"
        : "+f"(c[0]), "+f"(c[1]), "+f"(c[2]), "+f"(c[3])
        : "r"(a[0]), "r"(a[1]), "r"(a[2]), "r"(a[3]), "r"(b[0]), "r"(b[1]));
}

// ======================= 1) transpose x (b,l,m) -> (b,m,l) =================
__global__ void transpose_kernel(const float* __restrict__ x) {
    __shared__ float tile[32][33];
    int b  = blockIdx.z;
    int l0 = blockIdx.x * 32;
    int m0 = blockIdx.y * 32;
    int tx = threadIdx.x, ty = threadIdx.y;
#pragma unroll
    for (int j = 0; j < 32; j += 8)
        tile[ty + j][tx] = x[(b * LEN + l0 + ty + j) * DM + m0 + tx];
    __syncthreads();
#pragma unroll
    for (int j = 0; j < 32; j += 8)
        g_xt[(b * DM + m0 + ty + j) * LEN + l0 + tx] = tile[tx][ty + j];
}

// ======================= 2) G = C @ B =====================================
__global__ void gmat_kernel(const float* __restrict__ Bm,
                            const float* __restrict__ Cm) {
    __shared__ float c_s[DS];
    int m = blockIdx.x;
    int k = threadIdx.x;
    c_s[k] = Cm[m * DS + k];
    __syncthreads();
    float g = 0.f;
#pragma unroll 8
    for (int i = 0; i < DS; ++i)
        g = fmaf(c_s[i], Bm[i * DM + k], g);
    g_G[m * DS + k] = g;
}

// ======================= 3) fused psum + kern (proven) =====================
__global__ void __launch_bounds__(256) pk_kernel(const float* __restrict__ Lam,
                                                 const float* __restrict__ log_dt) {
    __shared__ float Gs[DM][DS];     // 64KB, [m][k]
    __shared__ float ps[DS][33];     // [k][l], pad 33
    __shared__ float dt_s[DM];
    const int tid = threadIdx.x;
    const int l0  = blockIdx.x * 32;

    if (tid < DM) dt_s[tid] = __expf(log_dt[tid]);
    for (int i = tid * 4; i < DM * DS; i += 256 * 4)
        *(float4*)(&Gs[0][0] + i) = *(const float4*)(g_G + i);
    __syncthreads();

    for (int e = tid; e < DS * 32; e += 256) {
        int k = e >> 5, l = e & 31;
        float a = Lam[k] * (float)(l0 + l);
        float s = 0.f;
#pragma unroll 8
        for (int mp = 0; mp < DM; ++mp)
            s += __expf(dt_s[mp] * a);
        ps[k][l] = s;
    }
    __syncthreads();

    const int l  = tid & 31;
    const int m0 = (tid >> 5) * 16;
    float acc[16];
#pragma unroll
    for (int i = 0; i < 16; ++i) acc[i] = 0.f;
#pragma unroll 4
    for (int k = 0; k < DS; ++k) {
        float p = ps[k][l];
#pragma unroll
        for (int i = 0; i < 16; ++i)
            acc[i] = fmaf(Gs[m0 + i][k], p, acc[i]);
    }
#pragma unroll
    for (int i = 0; i < 16; ++i)
        g_kern[(m0 + i) * LEN + l0 + l] = acc[i];
}

// ======================= 4) tensor-core conv (fp16 HMMA, 512 thr) ==========
// Per CTA (one m): Y[i, nb] (128 x 256), nb = 8*j + b.
//   Y[:, 8j+b] = sum_{d<=j} T_d(128x128) @ X[:, 8(j-d)+b]
// 16 warps: warp-group wg = wid/8 owns m-tiles [4wg, 4wg+4); within-group
// warp w8 owns balanced slots {w8, 15-w8, 16+w8, 31-w8} (66 per warp).
// Single product Kh*Xh (rel_err ~2.9e-4 measured).
#define XSTRIDE 68                        // u32 row stride -> conflict-free
#define KPOFF   136
#define KPSZ    4240
#define SM_CONV ((256 * XSTRIDE + KPSZ) * 4)   // 86592 B
#define CNT 512

__global__ void __launch_bounds__(CNT, 1) conv_mma_kernel() {
    extern __shared__ char smem[];
    uint32_t* XH  = (uint32_t*)smem;             // [256][68]
    uint32_t* KPH = XH + 256 * XSTRIDE;          // logical index c+KPOFF

    const int tid = threadIdx.x;
    const int m   = blockIdx.x;

    // ---- fill kp array (reversed-pair kernel, fp16) ----
    const float* krow = g_kern + m * LEN;
    for (int i = tid; i < KPSZ; i += CNT) {
        int c = i - KPOFF;
        float f0 = (c >= 0 && c < LEN) ? krow[c] : 0.f;
        float f1 = (c >= 1 && c <= LEN) ? krow[c - 1] : 0.f;
        KPH[i] = h2_pack(f0, f1);
    }
    // ---- fill X (nb-major, pairs along u), fp16 ----
    for (int idx = tid; idx < 256 * 64; idx += CNT) {
        int nb = idx >> 6, qq = idx & 63;
        int b = nb & 7, j = nb >> 3;
        float2 v = *(const float2*)(g_xt + (size_t)(b * DM + m) * LEN + j * S + 2 * qq);
        XH[nb * XSTRIDE + qq] = h2_pack(v.x, v.y);
    }
    __syncthreads();

    const int wid  = tid >> 5;
    const int wg   = wid >> 3;      // warp-group -> m-tile half
    const int w8   = wid & 7;
    const int lane = tid & 31;
    const int gq   = lane >> 2;     // group row
    const int tq   = lane & 3;      // thread in group

    const int sTab[4] = {w8, 15 - w8, 16 + w8, 31 - w8};   // balanced slots
    const int mtOff = 16 * 4 * wg;  // kp offset of this group's first m-tile

    float acc[4][4][4];             // [mtl][slot][reg]
#pragma unroll
    for (int mtl = 0; mtl < 4; ++mtl)
#pragma unroll
        for (int si = 0; si < 4; ++si)
#pragma unroll
            for (int r = 0; r < 4; ++r) acc[mtl][si][r] = 0.f;

    const int dmax = 31 - w8;       // largest s this warp owns
    for (int d = 0; d <= dmax; ++d) {
        for (int ks = 0; ks < 8; ++ks) {
            const int u0 = 16 * ks;
            // B fragments for the warp's valid column tiles
            uint32_t bh[4][2];
#pragma unroll
            for (int si = 0; si < 4; ++si) {
                int s = sTab[si];
                if (s >= d) {
                    int xi = (8 * (s - d) + gq) * XSTRIDE + 8 * ks + tq;
                    bh[si][0] = XH[xi]; bh[si][1] = XH[xi + 4];
                }
            }
            // rolling A fragments across this group's 4 m-tiles
            const int C0 = d * S + gq - 2 * tq - u0 + KPOFF + mtOff;
            uint32_t ahm = KPH[C0 - 8], ah0 = KPH[C0], ahp = KPH[C0 + 8];
#pragma unroll
            for (int mtl = 0; mtl < 4; ++mtl) {
                uint32_t ah[4] = {ah0, ahp, ahm, ah0};
#pragma unroll
                for (int si = 0; si < 4; ++si) {
                    int s = sTab[si];
                    if (s >= d)
                        mma16816(acc[mtl][si], ah, bh[si]);
                }
                if (mtl < 3) {
                    int Cn = C0 + 16 * (mtl + 1);
                    ahm = ahp; ah0 = KPH[Cn]; ahp = KPH[Cn + 8];
                }
            }
        }
    }

    // ---- epilogue: C frags -> g_y (m, b, l) ----
#pragma unroll
    for (int mtl = 0; mtl < 4; ++mtl)
#pragma unroll
        for (int si = 0; si < 4; ++si) {
            int s = sTab[si];
            int l = S * s + 16 * (4 * wg + mtl) + gq;
            size_t b0 = (size_t)(m * 8 + 2 * tq) * LEN;
            size_t b1 = (size_t)(m * 8 + 2 * tq + 1) * LEN;
            g_y[b0 + l]     = acc[mtl][si][0];
            g_y[b1 + l]     = acc[mtl][si][1];
            g_y[b0 + l + 8] = acc[mtl][si][2];
            g_y[b1 + l + 8] = acc[mtl][si][3];
        }
}

// ======================= 5) epilogue: transpose + skip =====================
__global__ void ytrans_kernel(const float* __restrict__ Dv,
                              float* __restrict__ out) {
    __shared__ float tile[32][33];
    int b  = blockIdx.z;
    int l0 = blockIdx.x * 32;
    int m0 = blockIdx.y * 32;
    int tx = threadIdx.x, ty = threadIdx.y;
#pragma unroll
    for (int j = 0; j < 32; j += 8) {
        int mm = m0 + ty + j;
        float y  = g_y[(size_t)(mm * 8 + b) * LEN + l0 + tx];
        float xv = g_xt[(size_t)(b * DM + mm) * LEN + l0 + tx];
        tile[ty + j][tx] = fmaf(Dv[mm], xv, y);
    }
    __syncthreads();
#pragma unroll
    for (int j = 0; j < 32; j += 8)
        out[(size_t)(b * LEN + l0 + ty + j) * DM + m0 + tx] = tile[tx][ty + j];
}

extern "C" void kernel_launch(void* const* d_in, const int* in_sizes, int n_in,
                              void* d_out, int out_size) {
    const float* x      = (const float*)d_in[0];  // (8, 4096, 128)
    const float* Lam    = (const float*)d_in[1];
    const float* Bm     = (const float*)d_in[2];
    const float* Cm     = (const float*)d_in[3];
    const float* Dv     = (const float*)d_in[4];
    const float* log_dt = (const float*)d_in[5];
    float* out = (float*)d_out;

    cudaFuncSetAttribute(conv_mma_kernel,
                         cudaFuncAttributeMaxDynamicSharedMemorySize, SM_CONV);

    transpose_kernel<<<dim3(LEN / 32, DM / 32, BSZ), dim3(32, 8)>>>(x);
    gmat_kernel<<<DM, DS>>>(Bm, Cm);
    pk_kernel<<<LEN / 32, 256>>>(Lam, log_dt);
    conv_mma_kernel<<<DM, CNT, SM_CONV>>>();
    ytrans_kernel<<<dim3(LEN / 32, DM / 32, BSZ), dim3(32, 8)>>>(Dv, out);
}

// round 15
// speedup vs baseline: 7.6475x; 1.2991x over previous
#include <cuda_runtime.h>
#include <cuda_bf16.h>
#include <cuda_fp16.h>
#include <cstdint>

#define BSZ 8
#define LEN 4096
#define DM  128
#define DS  128
#define S   128          // time block
#define NB  32           // LEN/S

// -------- scratch (__device__ globals; no allocation allowed) --------
__device__ float g_xt[BSZ * DM * LEN];    // x transposed to (b, m, l)
__device__ float g_kern[DM * LEN];
__device__ float g_G[DM * DS];
__device__ float g_y[DM * BSZ * LEN];     // conv result, (m, b, l)

__device__ __forceinline__ uint32_t h2_pack(float a, float b) {
    __half2 t = __floats2half2_rn(a, b);   // a -> low, b -> high
    return *reinterpret_cast<uint32_t*>(&t);
}

// m16n8k16 row.col f32.f16.f16.f32 (legacy HMMA, valid on compute_103 base)
__device__ __forceinline__ void mma16816(float* c, const uint32_t* a,
                                         const uint32_t* b) {
    asm volatile(
        "mma.sync.aligned.m16n8k16.row.col.f32.f16.f16.f32 "
        "{%0,%1,%2,%3}, {%4,%5,%6,%7}, {%8,%9}, {%0,%1,%2,%3};"
        : "+f"(c[0]), "+f"(c[1]), "+f"(c[2]), "+f"(c[3])
        : "r"(a[0]), "r"(a[1]), "r"(a[2]), "r"(a[3]), "r"(b[0]), "r"(b[1]));
}

// ======================= 1) transpose x (b,l,m) -> (b,m,l) =================
__global__ void transpose_kernel(const float* __restrict__ x) {
    __shared__ float tile[32][33];
    int b  = blockIdx.z;
    int l0 = blockIdx.x * 32;
    int m0 = blockIdx.y * 32;
    int tx = threadIdx.x, ty = threadIdx.y;
#pragma unroll
    for (int j = 0; j < 32; j += 8)
        tile[ty + j][tx] = x[(b * LEN + l0 + ty + j) * DM + m0 + tx];
    __syncthreads();
#pragma unroll
    for (int j = 0; j < 32; j += 8)
        g_xt[(b * DM + m0 + ty + j) * LEN + l0 + tx] = tile[tx][ty + j];
}

// ======================= 2) G = C @ B =====================================
__global__ void gmat_kernel(const float* __restrict__ Bm,
                            const float* __restrict__ Cm) {
    __shared__ float c_s[DS];
    int m = blockIdx.x;
    int k = threadIdx.x;
    c_s[k] = Cm[m * DS + k];
    __syncthreads();
    float g = 0.f;
#pragma unroll 8
    for (int i = 0; i < DS; ++i)
        g = fmaf(c_s[i], Bm[i * DM + k], g);
    g_G[m * DS + k] = g;
}

// ======================= 3) fused psum + kern (proven) =====================
__global__ void __launch_bounds__(256) pk_kernel(const float* __restrict__ Lam,
                                                 const float* __restrict__ log_dt) {
    __shared__ float Gs[DM][DS];     // 64KB, [m][k]
    __shared__ float ps[DS][33];     // [k][l], pad 33
    __shared__ float dt_s[DM];
    const int tid = threadIdx.x;
    const int l0  = blockIdx.x * 32;

    if (tid < DM) dt_s[tid] = __expf(log_dt[tid]);
    for (int i = tid * 4; i < DM * DS; i += 256 * 4)
        *(float4*)(&Gs[0][0] + i) = *(const float4*)(g_G + i);
    __syncthreads();

    for (int e = tid; e < DS * 32; e += 256) {
        int k = e >> 5, l = e & 31;
        float a = Lam[k] * (float)(l0 + l);
        float s = 0.f;
#pragma unroll 8
        for (int mp = 0; mp < DM; ++mp)
            s += __expf(dt_s[mp] * a);
        ps[k][l] = s;
    }
    __syncthreads();

    const int l  = tid & 31;
    const int m0 = (tid >> 5) * 16;
    float acc[16];
#pragma unroll
    for (int i = 0; i < 16; ++i) acc[i] = 0.f;
#pragma unroll 4
    for (int k = 0; k < DS; ++k) {
        float p = ps[k][l];
#pragma unroll
        for (int i = 0; i < 16; ++i)
            acc[i] = fmaf(Gs[m0 + i][k], p, acc[i]);
    }
#pragma unroll
    for (int i = 0; i < 16; ++i)
        g_kern[(m0 + i) * LEN + l0 + l] = acc[i];
}

// ======================= 4) tensor-core conv (fp16 HMMA) ===================
// Per CTA (one m): Y[i, nb] (128 x 256), nb = 8*j + b.
// 16 warps: warp-group wg = wid/8 owns m-tiles [4wg, 4wg+4); within-group
// warp w8 owns slots {w8, 15-w8, 16+w8, 31-w8} (66 d-iterations each).
// This round: u64 operand loads (B frag = 1 LDS.64 via XI pairing; A frag =
// 2 LDS.64 via KP2 pairing) + guard-free d-range decomposition (4/3/2/1
// slots per range) + ks unroll for LDS/HMMA overlap.
#define KPOFF   136
#define KPSZ    4240
#define XI_BYTES (256 * 34 * 8)                       // 69632
#define SM_CONV  (XI_BYTES + KPSZ * 8)                // 103552 B
#define CNT 512

template <int NS>
__device__ __forceinline__ void conv_d_iter(
    int d, const int* sl, const int* ix,
    const uint64_t* __restrict__ XI, const uint64_t* __restrict__ KP2,
    int gq, int tq, int mtOff, float (*acc)[4][4])
{
#pragma unroll 2
    for (int ks = 0; ks < 8; ++ks) {
        uint64_t bv[NS];
#pragma unroll
        for (int si = 0; si < NS; ++si)
            bv[si] = XI[(8 * (sl[si] - d) + gq) * 34 + 4 * ks + tq];
        const int C0 = d * S + gq - 2 * tq - 16 * ks + KPOFF + mtOff;
#pragma unroll
        for (int mtl = 0; mtl < 4; ++mtl) {
            uint64_t p0 = KP2[C0 + 16 * mtl - 8];    // (pair(c-8), pair(c))
            uint64_t p1 = KP2[C0 + 16 * mtl];        // (pair(c),   pair(c+8))
            uint32_t ahm = (uint32_t)p0;
            uint32_t ah0 = (uint32_t)(p0 >> 32);
            uint32_t ahp = (uint32_t)(p1 >> 32);
            uint32_t ah[4] = {ah0, ahp, ahm, ah0};
#pragma unroll
            for (int si = 0; si < NS; ++si) {
                uint32_t b2[2] = {(uint32_t)bv[si], (uint32_t)(bv[si] >> 32)};
                mma16816(acc[mtl][ix[si]], ah, b2);
            }
        }
    }
}

__global__ void __launch_bounds__(CNT, 1) conv_mma_kernel() {
    extern __shared__ char smem[];
    uint32_t* XIu  = (uint32_t*)smem;                   // [256][68] u32 view
    uint32_t* KP2u = XIu + 256 * 68;
    const uint64_t* XI  = (const uint64_t*)smem;
    const uint64_t* KP2 = (const uint64_t*)(smem + XI_BYTES);

    const int tid = threadIdx.x;
    const int m   = blockIdx.x;

    // ---- KP2[i] = (pair(c), pair(c+8)), pair(c) = h2(k[c], k[c-1]) ----
    const float* krow = g_kern + m * LEN;
    for (int i = tid; i < KPSZ; i += CNT) {
        int c = i - KPOFF;
        float f0 = (c >= 0 && c < LEN) ? krow[c] : 0.f;
        float f1 = (c >= 1 && c <= LEN) ? krow[c - 1] : 0.f;
        uint32_t p = h2_pack(f0, f1);
        KP2u[2 * i] = p;                       // lo of entry i
        if (i >= 8) KP2u[2 * (i - 8) + 1] = p; // hi of entry i-8
    }
    // ---- XI[nb][4ks+tq] = (xpair(16ks+2tq), xpair(16ks+2tq+8)) ----
    for (int idx = tid; idx < 256 * 64; idx += CNT) {
        int nb = idx >> 6, qq = idx & 63;
        int b = nb & 7, j = nb >> 3;
        float2 v = *(const float2*)(g_xt + (size_t)(b * DM + m) * LEN + j * S + 2 * qq);
        int ks = qq >> 3, t = qq & 7;
        XIu[nb * 68 + 8 * ks + 2 * (t & 3) + (t >> 2)] = h2_pack(v.x, v.y);
    }
    __syncthreads();

    const int wid  = tid >> 5;
    const int wg   = wid >> 3;      // warp-group -> m-tile half
    const int w8   = wid & 7;
    const int lane = tid & 31;
    const int gq   = lane >> 2;
    const int tq   = lane & 3;
    const int mtOff = 64 * wg;

    const int s0 = w8, s1 = 15 - w8, s2 = 16 + w8, s3 = 31 - w8;

    float acc[4][4][4];             // [mtl][slot][reg]
#pragma unroll
    for (int mtl = 0; mtl < 4; ++mtl)
#pragma unroll
        for (int si = 0; si < 4; ++si)
#pragma unroll
            for (int r = 0; r < 4; ++r) acc[mtl][si][r] = 0.f;

    {   // range 1: d in [0, w8] -> all 4 slots valid
        const int sl[4] = {s0, s1, s2, s3}, ix[4] = {0, 1, 2, 3};
        for (int d = 0; d <= w8; ++d)
            conv_d_iter<4>(d, sl, ix, XI, KP2, gq, tq, mtOff, acc);
    }
    {   // range 2: d in (w8, 15-w8] -> slots {s1, s2, s3}
        const int sl[3] = {s1, s2, s3}, ix[3] = {1, 2, 3};
        for (int d = w8 + 1; d <= 15 - w8; ++d)
            conv_d_iter<3>(d, sl, ix, XI, KP2, gq, tq, mtOff, acc);
    }
    {   // range 3: d in (15-w8, 16+w8] -> slots {s2, s3}
        const int sl[2] = {s2, s3}, ix[2] = {2, 3};
        for (int d = 16 - w8; d <= 16 + w8; ++d)
            conv_d_iter<2>(d, sl, ix, XI, KP2, gq, tq, mtOff, acc);
    }
    {   // range 4: d in (16+w8, 31-w8] -> slot {s3}
        const int sl[1] = {s3}, ix[1] = {3};
        for (int d = 17 + w8; d <= 31 - w8; ++d)
            conv_d_iter<1>(d, sl, ix, XI, KP2, gq, tq, mtOff, acc);
    }

    // ---- epilogue: C frags -> g_y (m, b, l) ----
    const int sTab[4] = {s0, s1, s2, s3};
#pragma unroll
    for (int mtl = 0; mtl < 4; ++mtl)
#pragma unroll
        for (int si = 0; si < 4; ++si) {
            int s = sTab[si];
            int l = S * s + 16 * (4 * wg + mtl) + gq;
            size_t b0 = (size_t)(m * 8 + 2 * tq) * LEN;
            size_t b1 = (size_t)(m * 8 + 2 * tq + 1) * LEN;
            g_y[b0 + l]     = acc[mtl][si][0];
            g_y[b1 + l]     = acc[mtl][si][1];
            g_y[b0 + l + 8] = acc[mtl][si][2];
            g_y[b1 + l + 8] = acc[mtl][si][3];
        }
}

// ======================= 5) epilogue: transpose + skip =====================
__global__ void ytrans_kernel(const float* __restrict__ Dv,
                              float* __restrict__ out) {
    __shared__ float tile[32][33];
    int b  = blockIdx.z;
    int l0 = blockIdx.x * 32;
    int m0 = blockIdx.y * 32;
    int tx = threadIdx.x, ty = threadIdx.y;
#pragma unroll
    for (int j = 0; j < 32; j += 8) {
        int mm = m0 + ty + j;
        float y  = g_y[(size_t)(mm * 8 + b) * LEN + l0 + tx];
        float xv = g_xt[(size_t)(b * DM + mm) * LEN + l0 + tx];
        tile[ty + j][tx] = fmaf(Dv[mm], xv, y);
    }
    __syncthreads();
#pragma unroll
    for (int j = 0; j < 32; j += 8)
        out[(size_t)(b * LEN + l0 + ty + j) * DM + m0 + tx] = tile[tx][ty + j];
}

extern "C" void kernel_launch(void* const* d_in, const int* in_sizes, int n_in,
                              void* d_out, int out_size) {
    const float* x      = (const float*)d_in[0];  // (8, 4096, 128)
    const float* Lam    = (const float*)d_in[1];
    const float* Bm     = (const float*)d_in[2];
    const float* Cm     = (const float*)d_in[3];
    const float* Dv     = (const float*)d_in[4];
    const float* log_dt = (const float*)d_in[5];
    float* out = (float*)d_out;

    cudaFuncSetAttribute(conv_mma_kernel,
                         cudaFuncAttributeMaxDynamicSharedMemorySize, SM_CONV);

    transpose_kernel<<<dim3(LEN / 32, DM / 32, BSZ), dim3(32, 8)>>>(x);
    gmat_kernel<<<DM, DS>>>(Bm, Cm);
    pk_kernel<<<LEN / 32, 256>>>(Lam, log_dt);
    conv_mma_kernel<<<DM, CNT, SM_CONV>>>();
    ytrans_kernel<<<dim3(LEN / 32, DM / 32, BSZ), dim3(32, 8)>>>(Dv, out);
}

// round 16
// speedup vs baseline: 7.7927x; 1.0190x over previous
#include <cuda_runtime.h>
#include <cuda_bf16.h>
#include <cuda_fp16.h>
#include <cstdint>

#define BSZ 8
#define LEN 4096
#define DM  128
#define DS  128
#define S   128          // time block
#define NB  32           // LEN/S

// -------- scratch (__device__ globals; no allocation allowed) --------
__device__ float g_xt[BSZ * DM * LEN];    // x transposed to (b, m, l)
__device__ float g_kern[DM * LEN];
__device__ float g_G[DM * DS];
__device__ float g_y[DM * BSZ * LEN];     // conv result, (m, b, l)

__device__ __forceinline__ uint32_t h2_pack(float a, float b) {
    __half2 t = __floats2half2_rn(a, b);   // a -> low, b -> high
    return *reinterpret_cast<uint32_t*>(&t);
}

using u64 = unsigned long long;
__device__ __forceinline__ u64 pk2(float lo, float hi) {
    u64 r; asm("mov.b64 %0, {%1, %2};" : "=l"(r) : "f"(lo), "f"(hi)); return r;
}
__device__ __forceinline__ void add2(u64 &d, u64 a) {
    asm("add.rn.f32x2 %0, %0, %1;" : "+l"(d) : "l"(a));
}
__device__ __forceinline__ void mul2(u64 &d, u64 a) {
    asm("mul.rn.f32x2 %0, %0, %1;" : "+l"(d) : "l"(a));
}

// m16n8k16 row.col f32.f16.f16.f32 (legacy HMMA, valid on compute_103 base)
__device__ __forceinline__ void mma16816(float* c, const uint32_t* a,
                                         const uint32_t* b) {
    asm volatile(
        "mma.sync.aligned.m16n8k16.row.col.f32.f16.f16.f32 "
        "{%0,%1,%2,%3}, {%4,%5,%6,%7}, {%8,%9}, {%0,%1,%2,%3};"
        : "+f"(c[0]), "+f"(c[1]), "+f"(c[2]), "+f"(c[3])
        : "r"(a[0]), "r"(a[1]), "r"(a[2]), "r"(a[3]), "r"(b[0]), "r"(b[1]));
}

// ======================= 1) transpose x (b,l,m) -> (b,m,l) =================
__global__ void transpose_kernel(const float* __restrict__ x) {
    __shared__ float tile[32][33];
    int b  = blockIdx.z;
    int l0 = blockIdx.x * 32;
    int m0 = blockIdx.y * 32;
    int tx = threadIdx.x, ty = threadIdx.y;
#pragma unroll
    for (int j = 0; j < 32; j += 8)
        tile[ty + j][tx] = x[(b * LEN + l0 + ty + j) * DM + m0 + tx];
    __syncthreads();
#pragma unroll
    for (int j = 0; j < 32; j += 8)
        g_xt[(b * DM + m0 + ty + j) * LEN + l0 + tx] = tile[tx][ty + j];
}

// ======================= 2) G = C @ B =====================================
__global__ void gmat_kernel(const float* __restrict__ Bm,
                            const float* __restrict__ Cm) {
    __shared__ float c_s[DS];
    int m = blockIdx.x;
    int k = threadIdx.x;
    c_s[k] = Cm[m * DS + k];
    __syncthreads();
    float g = 0.f;
#pragma unroll 8
    for (int i = 0; i < DS; ++i)
        g = fmaf(c_s[i], Bm[i * DM + k], g);
    g_G[m * DS + k] = g;
}

// ======================= 3) fused psum + kern (geometric stepping) =========
// Phase A: thread (k = tid>>1, half = tid&1) accumulates 64 m' over 32 l via
// p(l0+i) = exp(r*l0) * exp(r)^i, f32x2-packed pairs (2 exp per (k,m')).
// Phase B: kern[m,l] = G @ psum with G resident in smem.
__global__ void __launch_bounds__(256) pk_kernel(const float* __restrict__ Lam,
                                                 const float* __restrict__ log_dt) {
    __shared__ float Gs[DM][DS];         // 64KB, [m][k]
    __shared__ float ps[2][DS][34];      // [half][k][l], 8B-aligned rows
    __shared__ float dt_s[DM];
    const int tid = threadIdx.x;
    const int l0  = blockIdx.x * 32;

    if (tid < DM) dt_s[tid] = __expf(log_dt[tid]);
    for (int i = tid * 4; i < DM * DS; i += 256 * 4)
        *(float4*)(&Gs[0][0] + i) = *(const float4*)(g_G + i);
    __syncthreads();

    {   // Phase A
        const int k    = tid >> 1;
        const int half = tid & 1;
        const float Lk = Lam[k];
        u64 a2[16];
#pragma unroll
        for (int j = 0; j < 16; ++j) a2[j] = 0ull;
        for (int mp = half * 64; mp < half * 64 + 64; ++mp) {
            float r  = dt_s[mp] * Lk;           // <= 0
            float p  = __expf(r * (float)l0);
            float s  = __expf(r);
            u64 pv = pk2(p, p * s);
            u64 sv = pk2(s * s, s * s);
#pragma unroll
            for (int j = 0; j < 16; ++j) { add2(a2[j], pv); mul2(pv, sv); }
        }
        u64* row = (u64*)&ps[half][k][0];
#pragma unroll
        for (int j = 0; j < 16; ++j) row[j] = a2[j];
    }
    __syncthreads();

    {   // Phase B
        const int l  = tid & 31;
        const int m0 = (tid >> 5) * 16;
        float acc[16];
#pragma unroll
        for (int i = 0; i < 16; ++i) acc[i] = 0.f;
#pragma unroll 4
        for (int k = 0; k < DS; ++k) {
            float p = ps[0][k][l] + ps[1][k][l];
#pragma unroll
            for (int i = 0; i < 16; ++i)
                acc[i] = fmaf(Gs[m0 + i][k], p, acc[i]);
        }
#pragma unroll
        for (int i = 0; i < 16; ++i)
            g_kern[(m0 + i) * LEN + l0 + l] = acc[i];
    }
}

// ======================= 4) tensor-core conv (fp16 HMMA) ===================
// Per CTA (one m): Y[i, nb] (128 x 256), nb = 8*j + b.
// 16 warps: warp-group wg = wid/8 owns m-tiles [4wg, 4wg+4); within-group
// warp w8 owns slots {w8, 15-w8, 16+w8, 31-w8} (66 d-iterations each).
// A-fragment delta-reuse: A index depends only on delta = mtl - ks in [-7,3]
// -> 12 LDS.64 per d (pairs P[0..11]) shared across all 32 (ks,mtl) combos.
#define KPOFF   136
#define KPSZ    4256
#define XI_BYTES (256 * 34 * 8)                       // 69632
#define SM_CONV  (XI_BYTES + KPSZ * 8)                // 103680 B
#define CNT 512

template <int NS>
__device__ __forceinline__ void conv_d_iter(
    int d, const int* sl, const int* ix,
    const uint64_t* __restrict__ XI, const uint64_t* __restrict__ KP2,
    int gq, int tq, int mtOff, float (*acc)[4][4])
{
    // pair cache: pr[2j] = pair(base+16j-120), pr[2j+1] = pair(base+16j-112)
    const int base = d * S + gq - 2 * tq + KPOFF + mtOff;
    uint32_t pr[24];
#pragma unroll
    for (int j = 0; j < 12; ++j) {
        uint64_t pv = KP2[base + 16 * j - 120];
        pr[2 * j]     = (uint32_t)pv;
        pr[2 * j + 1] = (uint32_t)(pv >> 32);
    }
#pragma unroll 2
    for (int ks = 0; ks < 8; ++ks) {
        uint64_t bv[NS];
#pragma unroll
        for (int si = 0; si < NS; ++si)
            bv[si] = XI[(8 * (sl[si] - d) + gq) * 34 + 4 * ks + tq];
#pragma unroll
        for (int mtl = 0; mtl < 4; ++mtl) {
            const int j7 = mtl - ks + 7;            // delta + 7 in [0,10]
            // ahm = pair(base+16delta-8), ah0 = pair(base+16delta),
            // ahp = pair(base+16delta+8)
            uint32_t ah[4] = {pr[2 * j7 + 1], pr[2 * j7 + 2],
                              pr[2 * j7],     pr[2 * j7 + 1]};
#pragma unroll
            for (int si = 0; si < NS; ++si) {
                uint32_t b2[2] = {(uint32_t)bv[si], (uint32_t)(bv[si] >> 32)};
                mma16816(acc[mtl][ix[si]], ah, b2);
            }
        }
    }
}

__global__ void __launch_bounds__(CNT, 1) conv_mma_kernel() {
    extern __shared__ char smem[];
    uint32_t* XIu  = (uint32_t*)smem;                   // [256][68] u32 view
    uint32_t* KP2u = XIu + 256 * 68;
    const uint64_t* XI  = (const uint64_t*)smem;
    const uint64_t* KP2 = (const uint64_t*)(smem + XI_BYTES);

    const int tid = threadIdx.x;
    const int m   = blockIdx.x;

    // ---- KP2[i] = (pair(c), pair(c+8)), pair(c) = h2(k[c], k[c-1]) ----
    const float* krow = g_kern + m * LEN;
    for (int i = tid; i < KPSZ; i += CNT) {
        int c = i - KPOFF;
        float f0 = (c >= 0 && c < LEN) ? krow[c] : 0.f;
        float f1 = (c >= 1 && c <= LEN) ? krow[c - 1] : 0.f;
        uint32_t p = h2_pack(f0, f1);
        KP2u[2 * i] = p;                       // lo of entry i
        if (i >= 8) KP2u[2 * (i - 8) + 1] = p; // hi of entry i-8
    }
    // ---- XI[nb][4ks+tq] = (xpair(16ks+2tq), xpair(16ks+2tq+8)) ----
    for (int idx = tid; idx < 256 * 64; idx += CNT) {
        int nb = idx >> 6, qq = idx & 63;
        int b = nb & 7, j = nb >> 3;
        float2 v = *(const float2*)(g_xt + (size_t)(b * DM + m) * LEN + j * S + 2 * qq);
        int ks = qq >> 3, t = qq & 7;
        XIu[nb * 68 + 8 * ks + 2 * (t & 3) + (t >> 2)] = h2_pack(v.x, v.y);
    }
    __syncthreads();

    const int wid  = tid >> 5;
    const int wg   = wid >> 3;      // warp-group -> m-tile half
    const int w8   = wid & 7;
    const int lane = tid & 31;
    const int gq   = lane >> 2;
    const int tq   = lane & 3;
    const int mtOff = 64 * wg;

    const int s0 = w8, s1 = 15 - w8, s2 = 16 + w8, s3 = 31 - w8;

    float acc[4][4][4];             // [mtl][slot][reg]
#pragma unroll
    for (int mtl = 0; mtl < 4; ++mtl)
#pragma unroll
        for (int si = 0; si < 4; ++si)
#pragma unroll
            for (int r = 0; r < 4; ++r) acc[mtl][si][r] = 0.f;

    {   // range 1: d in [0, w8] -> all 4 slots valid
        const int sl[4] = {s0, s1, s2, s3}, ix[4] = {0, 1, 2, 3};
        for (int d = 0; d <= w8; ++d)
            conv_d_iter<4>(d, sl, ix, XI, KP2, gq, tq, mtOff, acc);
    }
    {   // range 2: d in (w8, 15-w8] -> slots {s1, s2, s3}
        const int sl[3] = {s1, s2, s3}, ix[3] = {1, 2, 3};
        for (int d = w8 + 1; d <= 15 - w8; ++d)
            conv_d_iter<3>(d, sl, ix, XI, KP2, gq, tq, mtOff, acc);
    }
    {   // range 3: d in (15-w8, 16+w8] -> slots {s2, s3}
        const int sl[2] = {s2, s3}, ix[2] = {2, 3};
        for (int d = 16 - w8; d <= 16 + w8; ++d)
            conv_d_iter<2>(d, sl, ix, XI, KP2, gq, tq, mtOff, acc);
    }
    {   // range 4: d in (16+w8, 31-w8] -> slot {s3}
        const int sl[1] = {s3}, ix[1] = {3};
        for (int d = 17 + w8; d <= 31 - w8; ++d)
            conv_d_iter<1>(d, sl, ix, XI, KP2, gq, tq, mtOff, acc);
    }

    // ---- epilogue: C frags -> g_y (m, b, l) ----
    const int sTab[4] = {s0, s1, s2, s3};
#pragma unroll
    for (int mtl = 0; mtl < 4; ++mtl)
#pragma unroll
        for (int si = 0; si < 4; ++si) {
            int s = sTab[si];
            int l = S * s + 16 * (4 * wg + mtl) + gq;
            size_t b0 = (size_t)(m * 8 + 2 * tq) * LEN;
            size_t b1 = (size_t)(m * 8 + 2 * tq + 1) * LEN;
            g_y[b0 + l]     = acc[mtl][si][0];
            g_y[b1 + l]     = acc[mtl][si][1];
            g_y[b0 + l + 8] = acc[mtl][si][2];
            g_y[b1 + l + 8] = acc[mtl][si][3];
        }
}

// ======================= 5) epilogue: transpose + skip =====================
__global__ void ytrans_kernel(const float* __restrict__ Dv,
                              float* __restrict__ out) {
    __shared__ float tile[32][33];
    int b  = blockIdx.z;
    int l0 = blockIdx.x * 32;
    int m0 = blockIdx.y * 32;
    int tx = threadIdx.x, ty = threadIdx.y;
#pragma unroll
    for (int j = 0; j < 32; j += 8) {
        int mm = m0 + ty + j;
        float y  = g_y[(size_t)(mm * 8 + b) * LEN + l0 + tx];
        float xv = g_xt[(size_t)(b * DM + mm) * LEN + l0 + tx];
        tile[ty + j][tx] = fmaf(Dv[mm], xv, y);
    }
    __syncthreads();
#pragma unroll
    for (int j = 0; j < 32; j += 8)
        out[(size_t)(b * LEN + l0 + ty + j) * DM + m0 + tx] = tile[tx][ty + j];
}

extern "C" void kernel_launch(void* const* d_in, const int* in_sizes, int n_in,
                              void* d_out, int out_size) {
    const float* x      = (const float*)d_in[0];  // (8, 4096, 128)
    const float* Lam    = (const float*)d_in[1];
    const float* Bm     = (const float*)d_in[2];
    const float* Cm     = (const float*)d_in[3];
    const float* Dv     = (const float*)d_in[4];
    const float* log_dt = (const float*)d_in[5];
    float* out = (float*)d_out;

    cudaFuncSetAttribute(conv_mma_kernel,
                         cudaFuncAttributeMaxDynamicSharedMemorySize, SM_CONV);

    transpose_kernel<<<dim3(LEN / 32, DM / 32, BSZ), dim3(32, 8)>>>(x);
    gmat_kernel<<<DM, DS>>>(Bm, Cm);
    pk_kernel<<<LEN / 32, 256>>>(Lam, log_dt);
    conv_mma_kernel<<<DM, CNT, SM_CONV>>>();
    ytrans_kernel<<<dim3(LEN / 32, DM / 32, BSZ), dim3(32, 8)>>>(Dv, out);
}

// round 17
// speedup vs baseline: 9.3312x; 1.1974x over previous
#include <cuda_runtime.h>
#include <cuda_bf16.h>
#include <cuda_fp16.h>
#include <cstdint>

#define BSZ 8
#define LEN 4096
#define DM  128
#define DS  128
#define S   128          // time block
#define NB  32           // LEN/S

// -------- scratch (__device__ globals; no allocation allowed) --------
__device__ float g_xt[BSZ * DM * LEN];    // x transposed to (b, m, l)
__device__ float g_kern[DM * LEN];
__device__ float g_G[DM * DS];
__device__ float g_y[DM * BSZ * LEN];     // conv result, (m, b, l)

__device__ __forceinline__ uint32_t h2_pack(float a, float b) {
    __half2 t = __floats2half2_rn(a, b);   // a -> low, b -> high
    return *reinterpret_cast<uint32_t*>(&t);
}

using u64 = unsigned long long;
__device__ __forceinline__ u64 pk2(float lo, float hi) {
    u64 r; asm("mov.b64 %0, {%1, %2};" : "=l"(r) : "f"(lo), "f"(hi)); return r;
}
__device__ __forceinline__ void add2(u64 &d, u64 a) {
    asm("add.rn.f32x2 %0, %0, %1;" : "+l"(d) : "l"(a));
}
__device__ __forceinline__ void mul2(u64 &d, u64 a) {
    asm("mul.rn.f32x2 %0, %0, %1;" : "+l"(d) : "l"(a));
}

// m16n8k16 row.col f32.f16.f16.f32 (legacy HMMA, valid on compute_103 base)
__device__ __forceinline__ void mma16816(float* c, const uint32_t* a,
                                         const uint32_t* b) {
    asm volatile(
        "mma.sync.aligned.m16n8k16.row.col.f32.f16.f16.f32 "
        "{%0,%1,%2,%3}, {%4,%5,%6,%7}, {%8,%9}, {%0,%1,%2,%3};"
        : "+f"(c[0]), "+f"(c[1]), "+f"(c[2]), "+f"(c[3])
        : "r"(a[0]), "r"(a[1]), "r"(a[2]), "r"(a[3]), "r"(b[0]), "r"(b[1]));
}

// ======================= 1) transpose x (b,l,m) -> (b,m,l) =================
__global__ void transpose_kernel(const float* __restrict__ x) {
    __shared__ float tile[32][33];
    int b  = blockIdx.z;
    int l0 = blockIdx.x * 32;
    int m0 = blockIdx.y * 32;
    int tx = threadIdx.x, ty = threadIdx.y;
#pragma unroll
    for (int j = 0; j < 32; j += 8)
        tile[ty + j][tx] = x[(b * LEN + l0 + ty + j) * DM + m0 + tx];
    __syncthreads();
#pragma unroll
    for (int j = 0; j < 32; j += 8)
        g_xt[(b * DM + m0 + ty + j) * LEN + l0 + tx] = tile[tx][ty + j];
}

// ======================= 2) G = C @ B =====================================
__global__ void gmat_kernel(const float* __restrict__ Bm,
                            const float* __restrict__ Cm) {
    __shared__ float c_s[DS];
    int m = blockIdx.x;
    int k = threadIdx.x;
    c_s[k] = Cm[m * DS + k];
    __syncthreads();
    float g = 0.f;
#pragma unroll 8
    for (int i = 0; i < DS; ++i)
        g = fmaf(c_s[i], Bm[i * DM + k], g);
    g_G[m * DS + k] = g;
}

// ======================= 3) fused psum + kern (R16 proven, geometric) ======
__global__ void __launch_bounds__(256) pk_kernel(const float* __restrict__ Lam,
                                                 const float* __restrict__ log_dt) {
    __shared__ float Gs[DM][DS];         // 64KB, [m][k]
    __shared__ float ps[2][DS][34];      // [half][k][l], 8B-aligned rows
    __shared__ float dt_s[DM];
    const int tid = threadIdx.x;
    const int l0  = blockIdx.x * 32;

    if (tid < DM) dt_s[tid] = __expf(log_dt[tid]);
    for (int i = tid * 4; i < DM * DS; i += 256 * 4)
        *(float4*)(&Gs[0][0] + i) = *(const float4*)(g_G + i);
    __syncthreads();

    {   // Phase A
        const int k    = tid >> 1;
        const int half = tid & 1;
        const float Lk = Lam[k];
        u64 a2[16];
#pragma unroll
        for (int j = 0; j < 16; ++j) a2[j] = 0ull;
        for (int mp = half * 64; mp < half * 64 + 64; ++mp) {
            float r  = dt_s[mp] * Lk;           // <= 0
            float p  = __expf(r * (float)l0);
            float s  = __expf(r);
            u64 pv = pk2(p, p * s);
            u64 sv = pk2(s * s, s * s);
#pragma unroll
            for (int j = 0; j < 16; ++j) { add2(a2[j], pv); mul2(pv, sv); }
        }
        u64* row = (u64*)&ps[half][k][0];
#pragma unroll
        for (int j = 0; j < 16; ++j) row[j] = a2[j];
    }
    __syncthreads();

    {   // Phase B
        const int l  = tid & 31;
        const int m0 = (tid >> 5) * 16;
        float acc[16];
#pragma unroll
        for (int i = 0; i < 16; ++i) acc[i] = 0.f;
#pragma unroll 4
        for (int k = 0; k < DS; ++k) {
            float p = ps[0][k][l] + ps[1][k][l];
#pragma unroll
            for (int i = 0; i < 16; ++i)
                acc[i] = fmaf(Gs[m0 + i][k], p, acc[i]);
        }
#pragma unroll
        for (int i = 0; i < 16; ++i)
            g_kern[(m0 + i) * LEN + l0 + l] = acc[i];
    }
}

// ======================= 4) tensor-core conv (R15 proven, 53.8us) ==========
// Per CTA (one m): Y[i, nb] (128 x 256), nb = 8*j + b.
// 16 warps: warp-group wg = wid/8 owns m-tiles [4wg, 4wg+4); within-group
// warp w8 owns slots {w8, 15-w8, 16+w8, 31-w8} (66 d-iterations each).
// u64 operand loads (B frag = 1 LDS.64 via XI pairing; A frag = 2 LDS.64
// via KP2 pairing) + guard-free d-range decomposition (4/3/2/1).
#define KPOFF   136
#define KPSZ    4240
#define XI_BYTES (256 * 34 * 8)                       // 69632
#define SM_CONV  (XI_BYTES + KPSZ * 8)                // 103552 B
#define CNT 512

template <int NS>
__device__ __forceinline__ void conv_d_iter(
    int d, const int* sl, const int* ix,
    const uint64_t* __restrict__ XI, const uint64_t* __restrict__ KP2,
    int gq, int tq, int mtOff, float (*acc)[4][4])
{
#pragma unroll 2
    for (int ks = 0; ks < 8; ++ks) {
        uint64_t bv[NS];
#pragma unroll
        for (int si = 0; si < NS; ++si)
            bv[si] = XI[(8 * (sl[si] - d) + gq) * 34 + 4 * ks + tq];
        const int C0 = d * S + gq - 2 * tq - 16 * ks + KPOFF + mtOff;
#pragma unroll
        for (int mtl = 0; mtl < 4; ++mtl) {
            uint64_t p0 = KP2[C0 + 16 * mtl - 8];    // (pair(c-8), pair(c))
            uint64_t p1 = KP2[C0 + 16 * mtl];        // (pair(c),   pair(c+8))
            uint32_t ahm = (uint32_t)p0;
            uint32_t ah0 = (uint32_t)(p0 >> 32);
            uint32_t ahp = (uint32_t)(p1 >> 32);
            uint32_t ah[4] = {ah0, ahp, ahm, ah0};
#pragma unroll
            for (int si = 0; si < NS; ++si) {
                uint32_t b2[2] = {(uint32_t)bv[si], (uint32_t)(bv[si] >> 32)};
                mma16816(acc[mtl][ix[si]], ah, b2);
            }
        }
    }
}

__global__ void __launch_bounds__(CNT, 1) conv_mma_kernel() {
    extern __shared__ char smem[];
    uint32_t* XIu  = (uint32_t*)smem;                   // [256][68] u32 view
    uint32_t* KP2u = XIu + 256 * 68;
    const uint64_t* XI  = (const uint64_t*)smem;
    const uint64_t* KP2 = (const uint64_t*)(smem + XI_BYTES);

    const int tid = threadIdx.x;
    const int m   = blockIdx.x;

    // ---- KP2[i] = (pair(c), pair(c+8)), pair(c) = h2(k[c], k[c-1]) ----
    const float* krow = g_kern + m * LEN;
    for (int i = tid; i < KPSZ; i += CNT) {
        int c = i - KPOFF;
        float f0 = (c >= 0 && c < LEN) ? krow[c] : 0.f;
        float f1 = (c >= 1 && c <= LEN) ? krow[c - 1] : 0.f;
        uint32_t p = h2_pack(f0, f1);
        KP2u[2 * i] = p;                       // lo of entry i
        if (i >= 8) KP2u[2 * (i - 8) + 1] = p; // hi of entry i-8
    }
    // ---- XI[nb][4ks+tq] = (xpair(16ks+2tq), xpair(16ks+2tq+8)) ----
    for (int idx = tid; idx < 256 * 64; idx += CNT) {
        int nb = idx >> 6, qq = idx & 63;
        int b = nb & 7, j = nb >> 3;
        float2 v = *(const float2*)(g_xt + (size_t)(b * DM + m) * LEN + j * S + 2 * qq);
        int ks = qq >> 3, t = qq & 7;
        XIu[nb * 68 + 8 * ks + 2 * (t & 3) + (t >> 2)] = h2_pack(v.x, v.y);
    }
    __syncthreads();

    const int wid  = tid >> 5;
    const int wg   = wid >> 3;      // warp-group -> m-tile half
    const int w8   = wid & 7;
    const int lane = tid & 31;
    const int gq   = lane >> 2;
    const int tq   = lane & 3;
    const int mtOff = 64 * wg;

    const int s0 = w8, s1 = 15 - w8, s2 = 16 + w8, s3 = 31 - w8;

    float acc[4][4][4];             // [mtl][slot][reg]
#pragma unroll
    for (int mtl = 0; mtl < 4; ++mtl)
#pragma unroll
        for (int si = 0; si < 4; ++si)
#pragma unroll
            for (int r = 0; r < 4; ++r) acc[mtl][si][r] = 0.f;

    {   // range 1: d in [0, w8] -> all 4 slots valid
        const int sl[4] = {s0, s1, s2, s3}, ix[4] = {0, 1, 2, 3};
        for (int d = 0; d <= w8; ++d)
            conv_d_iter<4>(d, sl, ix, XI, KP2, gq, tq, mtOff, acc);
    }
    {   // range 2: d in (w8, 15-w8] -> slots {s1, s2, s3}
        const int sl[3] = {s1, s2, s3}, ix[3] = {1, 2, 3};
        for (int d = w8 + 1; d <= 15 - w8; ++d)
            conv_d_iter<3>(d, sl, ix, XI, KP2, gq, tq, mtOff, acc);
    }
    {   // range 3: d in (15-w8, 16+w8] -> slots {s2, s3}
        const int sl[2] = {s2, s3}, ix[2] = {2, 3};
        for (int d = 16 - w8; d <= 16 + w8; ++d)
            conv_d_iter<2>(d, sl, ix, XI, KP2, gq, tq, mtOff, acc);
    }
    {   // range 4: d in (16+w8, 31-w8] -> slot {s3}
        const int sl[1] = {s3}, ix[1] = {3};
        for (int d = 17 + w8; d <= 31 - w8; ++d)
            conv_d_iter<1>(d, sl, ix, XI, KP2, gq, tq, mtOff, acc);
    }

    // ---- epilogue: C frags -> g_y (m, b, l) ----
    const int sTab[4] = {s0, s1, s2, s3};
#pragma unroll
    for (int mtl = 0; mtl < 4; ++mtl)
#pragma unroll
        for (int si = 0; si < 4; ++si) {
            int s = sTab[si];
            int l = S * s + 16 * (4 * wg + mtl) + gq;
            size_t b0 = (size_t)(m * 8 + 2 * tq) * LEN;
            size_t b1 = (size_t)(m * 8 + 2 * tq + 1) * LEN;
            g_y[b0 + l]     = acc[mtl][si][0];
            g_y[b1 + l]     = acc[mtl][si][1];
            g_y[b0 + l + 8] = acc[mtl][si][2];
            g_y[b1 + l + 8] = acc[mtl][si][3];
        }
}

// ======================= 5) epilogue: transpose + skip =====================
__global__ void ytrans_kernel(const float* __restrict__ Dv,
                              float* __restrict__ out) {
    __shared__ float tile[32][33];
    int b  = blockIdx.z;
    int l0 = blockIdx.x * 32;
    int m0 = blockIdx.y * 32;
    int tx = threadIdx.x, ty = threadIdx.y;
#pragma unroll
    for (int j = 0; j < 32; j += 8) {
        int mm = m0 + ty + j;
        float y  = g_y[(size_t)(mm * 8 + b) * LEN + l0 + tx];
        float xv = g_xt[(size_t)(b * DM + mm) * LEN + l0 + tx];
        tile[ty + j][tx] = fmaf(Dv[mm], xv, y);
    }
    __syncthreads();
#pragma unroll
    for (int j = 0; j < 32; j += 8)
        out[(size_t)(b * LEN + l0 + ty + j) * DM + m0 + tx] = tile[tx][ty + j];
}

extern "C" void kernel_launch(void* const* d_in, const int* in_sizes, int n_in,
                              void* d_out, int out_size) {
    const float* x      = (const float*)d_in[0];  // (8, 4096, 128)
    const float* Lam    = (const float*)d_in[1];
    const float* Bm     = (const float*)d_in[2];
    const float* Cm     = (const float*)d_in[3];
    const float* Dv     = (const float*)d_in[4];
    const float* log_dt = (const float*)d_in[5];
    float* out = (float*)d_out;

    cudaFuncSetAttribute(conv_mma_kernel,
                         cudaFuncAttributeMaxDynamicSharedMemorySize, SM_CONV);

    transpose_kernel<<<dim3(LEN / 32, DM / 32, BSZ), dim3(32, 8)>>>(x);
    gmat_kernel<<<DM, DS>>>(Bm, Cm);
    pk_kernel<<<LEN / 32, 256>>>(Lam, log_dt);
    conv_mma_kernel<<<DM, CNT, SM_CONV>>>();
    ytrans_kernel<<<dim3(LEN / 32, DM / 32, BSZ), dim3(32, 8)>>>(Dv, out);
}